// round 2
// baseline (speedup 1.0000x reference)
#include <cuda_runtime.h>

#define DM    1024
#define NH    16
#define HD    64
#define BATCH 2
#define SEQ   2048
#define MTOT  (BATCH*SEQ)   // 4096

// Scratch (allocation-free rule: __device__ globals)
__device__ float g_q [(long long)BATCH*NH*SEQ*HD];   // [b,h,s,hd]
__device__ float g_k [(long long)BATCH*NH*SEQ*HD];
__device__ float g_v [(long long)BATCH*NH*SEQ*HD];
__device__ float g_ao[(long long)MTOT*DM];           // [b,s,d]

// ---------------------------------------------------------------------------
// SGEMM: C[M,N] = A[M,K] @ W[K,N] + bias.  M=4096, N=K=1024.
// 128x128 block tile, K-tile 16, 256 threads, 8x8 per thread.
// MODE 0/1/2: write g_q/g_k/g_v in [b,h,s,hd] layout.
// MODE 3    : A is g_ao, write Cout linear [M,N].
// ---------------------------------------------------------------------------
template<int MODE>
__global__ void __launch_bounds__(256)
gemm128(const float* __restrict__ A, const float* __restrict__ W,
        const float* __restrict__ bias, float* __restrict__ Cout)
{
    const int K = DM, N = DM;
    __shared__ float As[16][128];   // transposed: As[k][m]
    __shared__ float Ws[16][128];   // Ws[k][n]

    const float* Ap = (MODE == 3) ? (const float*)g_ao : A;
    float* dst = (MODE == 0) ? g_q : (MODE == 1) ? g_k
               : (MODE == 2) ? g_v : Cout;

    const int t  = threadIdx.x;
    const int tx = t & 15, ty = t >> 4;
    const int bm = blockIdx.y * 128, bn = blockIdx.x * 128;

    float acc[8][8];
    #pragma unroll
    for (int i = 0; i < 8; i++)
        #pragma unroll
        for (int j = 0; j < 8; j++) acc[i][j] = 0.f;

    for (int k0 = 0; k0 < K; k0 += 16) {
        #pragma unroll
        for (int r = 0; r < 2; r++) {
            int lin = t + r * 256;
            int ar = lin >> 2, ac = (lin & 3) << 2;           // 128 rows x 16 cols
            float4 av = *(const float4*)&Ap[(size_t)(bm + ar) * K + k0 + ac];
            As[ac + 0][ar] = av.x; As[ac + 1][ar] = av.y;
            As[ac + 2][ar] = av.z; As[ac + 3][ar] = av.w;
            int wr = lin >> 5, wc = (lin & 31) << 2;          // 16 rows x 128 cols
            *(float4*)&Ws[wr][wc] =
                *(const float4*)&W[(size_t)(k0 + wr) * N + bn + wc];
        }
        __syncthreads();
        #pragma unroll
        for (int kk = 0; kk < 16; kk++) {
            float ra[8], rb[8];
            *(float4*)&ra[0] = *(float4*)&As[kk][ty * 8];
            *(float4*)&ra[4] = *(float4*)&As[kk][ty * 8 + 4];
            *(float4*)&rb[0] = *(float4*)&Ws[kk][tx * 8];
            *(float4*)&rb[4] = *(float4*)&Ws[kk][tx * 8 + 4];
            #pragma unroll
            for (int i = 0; i < 8; i++)
                #pragma unroll
                for (int j = 0; j < 8; j++)
                    acc[i][j] += ra[i] * rb[j];
        }
        __syncthreads();
    }

    #pragma unroll
    for (int i = 0; i < 8; i++) {
        int gr = bm + ty * 8 + i;
        #pragma unroll
        for (int j = 0; j < 8; j += 4) {
            int gc = bn + tx * 8 + j;
            float4 v;
            v.x = acc[i][j + 0] + bias[gc + 0];
            v.y = acc[i][j + 1] + bias[gc + 1];
            v.z = acc[i][j + 2] + bias[gc + 2];
            v.w = acc[i][j + 3] + bias[gc + 3];
            if (MODE <= 2) {
                int b = gr >> 11, s = gr & (SEQ - 1);
                int h = gc >> 6,  hd = gc & (HD - 1);
                *(float4*)&dst[((size_t)((b * NH + h) * SEQ + s)) * HD + hd] = v;
            } else {
                *(float4*)&dst[(size_t)gr * DM + gc] = v;
            }
        }
    }
}

// ---------------------------------------------------------------------------
// Flash attention, fp32. BQ=BK=64, 256 threads (16x16, 4x4 per thread).
// Online softmax; P staged through smem reusing the K buffer.
// grid: (SEQ/64 q-tiles, BATCH*NH)
// ---------------------------------------------------------------------------
#define ATTN_SMEM_FLOATS (4096*3 + 1024*2)   // 14336 floats = 57344 B

__global__ void __launch_bounds__(256)
attn_kernel()
{
    extern __shared__ float sm[];
    float* QsT    = sm;            // [d][q]   4096
    float* KP     = sm + 4096;     // KsT [d][k], later Ps [q][k]
    float* Vs     = sm + 8192;     // [k][d]
    float* redmax = sm + 12288;    // [64][16]
    float* redsum = sm + 13312;    // [64][16]

    const int t  = threadIdx.x;
    const int tx = t & 15, ty = t >> 4;
    const int qt = blockIdx.x;
    const int bh = blockIdx.y;
    const int q0 = qt * 64;

    const float* Qg = g_q + ((size_t)bh * SEQ + q0) * HD;
    const float* Kg = g_k + (size_t)bh * SEQ * HD;
    const float* Vg = g_v + (size_t)bh * SEQ * HD;

    // Load Q tile transposed: QsT[d*64 + row]
    #pragma unroll
    for (int r = 0; r < 4; r++) {
        int lin = t + r * 256;
        int row = lin >> 4, d0 = (lin & 15) << 2;
        float4 v = *(const float4*)&Qg[row * HD + d0];
        QsT[(d0 + 0) * 64 + row] = v.x; QsT[(d0 + 1) * 64 + row] = v.y;
        QsT[(d0 + 2) * 64 + row] = v.z; QsT[(d0 + 3) * 64 + row] = v.w;
    }

    float o[4][4];
    float m[4], l[4];
    #pragma unroll
    for (int i = 0; i < 4; i++) {
        m[i] = -1e30f; l[i] = 0.f;
        #pragma unroll
        for (int j = 0; j < 4; j++) o[i][j] = 0.f;
    }

    const int ntiles = qt + 1;   // causal: only k-tiles with k0 <= q0
    for (int kt = 0; kt < ntiles; kt++) {
        const int k0 = kt * 64;
        __syncthreads();   // prior PV reads of KP/Vs done
        #pragma unroll
        for (int r = 0; r < 4; r++) {
            int lin = t + r * 256;
            int row = lin >> 4, d0 = (lin & 15) << 2;
            float4 kv = *(const float4*)&Kg[(size_t)(k0 + row) * HD + d0];
            KP[(d0 + 0) * 64 + row] = kv.x; KP[(d0 + 1) * 64 + row] = kv.y;
            KP[(d0 + 2) * 64 + row] = kv.z; KP[(d0 + 3) * 64 + row] = kv.w;
            *(float4*)&Vs[row * HD + d0] =
                *(const float4*)&Vg[(size_t)(k0 + row) * HD + d0];
        }
        __syncthreads();

        // S = Q @ K^T  (4x4 per thread)
        float sacc[4][4];
        #pragma unroll
        for (int i = 0; i < 4; i++)
            #pragma unroll
            for (int j = 0; j < 4; j++) sacc[i][j] = 0.f;
        #pragma unroll 16
        for (int d = 0; d < 64; d++) {
            float4 qv = *(float4*)&QsT[d * 64 + ty * 4];
            float4 kv = *(float4*)&KP [d * 64 + tx * 4];
            float qa[4] = {qv.x, qv.y, qv.z, qv.w};
            float kb[4] = {kv.x, kv.y, kv.z, kv.w};
            #pragma unroll
            for (int i = 0; i < 4; i++)
                #pragma unroll
                for (int j = 0; j < 4; j++)
                    sacc[i][j] += qa[i] * kb[j];
        }

        // scale + causal mask + local row max
        float lm[4];
        #pragma unroll
        for (int i = 0; i < 4; i++) {
            int qg = q0 + ty * 4 + i;
            lm[i] = -1e30f;
            #pragma unroll
            for (int j = 0; j < 4; j++) {
                float s = sacc[i][j] * 0.125f;
                int kg = k0 + tx * 4 + j;
                if (kg > qg) s = -1e30f;
                sacc[i][j] = s;
                lm[i] = fmaxf(lm[i], s);
            }
            redmax[(ty * 4 + i) * 16 + tx] = lm[i];
        }
        __syncthreads();

        float mnew[4], corr[4];
        #pragma unroll
        for (int i = 0; i < 4; i++) {
            float rm = m[i];
            const float* rp = &redmax[(ty * 4 + i) * 16];
            #pragma unroll
            for (int c = 0; c < 16; c++) rm = fmaxf(rm, rp[c]);
            mnew[i] = rm;
            corr[i] = __expf(m[i] - rm);
            m[i] = rm;
        }
        // exp, local sums, stage P (into KP — safe: all S reads done)
        #pragma unroll
        for (int i = 0; i < 4; i++) {
            float ls = 0.f;
            #pragma unroll
            for (int j = 0; j < 4; j++) {
                float p = __expf(sacc[i][j] - mnew[i]);
                sacc[i][j] = p;
                ls += p;
            }
            redsum[(ty * 4 + i) * 16 + tx] = ls;
            float4 pv = make_float4(sacc[i][0], sacc[i][1], sacc[i][2], sacc[i][3]);
            *(float4*)&KP[(ty * 4 + i) * 64 + tx * 4] = pv;
            #pragma unroll
            for (int j = 0; j < 4; j++) o[i][j] *= corr[i];
        }
        __syncthreads();

        #pragma unroll
        for (int i = 0; i < 4; i++) {
            float s2 = 0.f;
            const float* rp = &redsum[(ty * 4 + i) * 16];
            #pragma unroll
            for (int c = 0; c < 16; c++) s2 += rp[c];
            l[i] = l[i] * corr[i] + s2;
        }

        // O += P @ V
        #pragma unroll 16
        for (int kk = 0; kk < 64; kk++) {
            float4 vv = *(float4*)&Vs[kk * 64 + tx * 4];
            float vb[4] = {vv.x, vv.y, vv.z, vv.w};
            float pv[4];
            #pragma unroll
            for (int i = 0; i < 4; i++)
                pv[i] = KP[(ty * 4 + i) * 64 + kk];
            #pragma unroll
            for (int i = 0; i < 4; i++)
                #pragma unroll
                for (int j = 0; j < 4; j++)
                    o[i][j] += pv[i] * vb[j];
        }
    }

    // epilogue: normalize, scatter to [b,s,d]
    const int b = bh >> 4, h = bh & (NH - 1);
    #pragma unroll
    for (int i = 0; i < 4; i++) {
        float inv = 1.f / l[i];
        int s = q0 + ty * 4 + i;
        float4 v = make_float4(o[i][0] * inv, o[i][1] * inv,
                               o[i][2] * inv, o[i][3] * inv);
        *(float4*)&g_ao[((size_t)(b * SEQ + s)) * DM + h * HD + tx * 4] = v;
    }
}

// ---------------------------------------------------------------------------
extern "C" void kernel_launch(void* const* d_in, const int* in_sizes, int n_in,
                              void* d_out, int out_size)
{
    const float* x  = (const float*)d_in[0];
    const float* Wq = (const float*)d_in[1];
    const float* bq = (const float*)d_in[2];
    const float* Wk = (const float*)d_in[3];
    const float* bk = (const float*)d_in[4];
    const float* Wv = (const float*)d_in[5];
    const float* bv = (const float*)d_in[6];
    const float* Wo = (const float*)d_in[7];
    const float* bo = (const float*)d_in[8];

    dim3 gg(DM / 128, MTOT / 128);   // (8, 32)

    gemm128<0><<<gg, 256>>>(x, Wq, bq, nullptr);
    gemm128<1><<<gg, 256>>>(x, Wk, bk, nullptr);
    gemm128<2><<<gg, 256>>>(x, Wv, bv, nullptr);

    const int smem_bytes = ATTN_SMEM_FLOATS * (int)sizeof(float);
    cudaFuncSetAttribute(attn_kernel,
                         cudaFuncAttributeMaxDynamicSharedMemorySize, smem_bytes);
    attn_kernel<<<dim3(SEQ / 64, BATCH * NH), 256, smem_bytes>>>();

    gemm128<3><<<gg, 256>>>(nullptr, Wo, bo, (float*)d_out);
}

// round 4
// speedup vs baseline: 1.4632x; 1.4632x over previous
#include <cuda_runtime.h>
#include <cstdint>

#define DM    1024
#define NH    16
#define HD    64
#define BATCH 2
#define SEQ   2048
#define MTOT  (BATCH*SEQ)   // 4096

// Scratch (allocation-free rule: __device__ globals)
__device__ float g_q [(long long)BATCH*NH*SEQ*HD];   // [b,h,s,hd]
__device__ float g_k [(long long)BATCH*NH*SEQ*HD];
__device__ float g_v [(long long)BATCH*NH*SEQ*HD];
__device__ float g_ao[(long long)MTOT*DM];           // [b,s,d]

__device__ __forceinline__ uint32_t f2tf32(float x) {
    uint32_t r;
    asm("cvt.rna.tf32.f32 %0, %1;" : "=r"(r) : "f"(x));
    return r;
}

__device__ __forceinline__ void mma_tf32(float c[4], uint32_t a0, uint32_t a1,
                                         uint32_t a2, uint32_t a3,
                                         uint32_t b0, uint32_t b1) {
    asm volatile(
        "mma.sync.aligned.m16n8k8.row.col.f32.tf32.tf32.f32 "
        "{%0,%1,%2,%3}, {%4,%5,%6,%7}, {%8,%9}, {%0,%1,%2,%3};"
        : "+f"(c[0]), "+f"(c[1]), "+f"(c[2]), "+f"(c[3])
        : "r"(a0), "r"(a1), "r"(a2), "r"(a3), "r"(b0), "r"(b1));
}

// ===========================================================================
// TF32 mma.sync GEMM: C[M,N] = A[M,1024] @ W[1024,N] + bias
// 128x128 CTA tile, 256 thr = 8 warps (2x4), warp tile 64x32.
// K-tile 32, double-buffered smem. A pitch 36 words, W pitch 132 words
// (conflict-free fragment loads).
// MODE 0: QKV (z selects W/bias, scatter to g_q/g_k/g_v [b,h,s,hd])
// MODE 3: O-proj (A = g_ao, linear out)
// ===========================================================================
#define APITCH 36
#define WPITCH 132
#define AWORDS (128*APITCH)          // 4608
#define WWORDS (32*WPITCH)           // 4224
#define BUFWORDS (AWORDS + WWORDS)   // 8832
#define GEMM_SMEM_BYTES (2*BUFWORDS*4)   // 70656

template<int MODE>
__global__ void __launch_bounds__(256)
gemm_mma(const float* __restrict__ A0,
         const float* __restrict__ W0, const float* __restrict__ b0,
         const float* __restrict__ W1, const float* __restrict__ b1,
         const float* __restrict__ W2, const float* __restrict__ b2,
         float* __restrict__ Cout)
{
    extern __shared__ float sm[];

    const int t   = threadIdx.x;
    const int wid = t >> 5, lane = t & 31;
    const int grp = lane >> 2, qid = lane & 3;
    const int wr  = wid & 1, wc = wid >> 1;      // warp 64-row block, 32-col block
    const int bn  = blockIdx.x * 128, bm = blockIdx.y * 128;

    const float* Ap;
    const float* W;
    const float* bias;
    float* dst;
    if (MODE == 3) {
        Ap = g_ao; W = W0; bias = b0; dst = Cout;
    } else {
        Ap = A0;
        int z = blockIdx.z;
        W    = (z == 0) ? W0 : (z == 1) ? W1 : W2;
        bias = (z == 0) ? b0 : (z == 1) ? b1 : b2;
        dst  = (z == 0) ? g_q : (z == 1) ? g_k : g_v;
    }

    float c[4][4][4];
    #pragma unroll
    for (int mt = 0; mt < 4; mt++)
        #pragma unroll
        for (int nt = 0; nt < 4; nt++)
            #pragma unroll
            for (int i = 0; i < 4; i++) c[mt][nt][i] = 0.f;

    // fill indices
    const int arow = t >> 3, ac4 = t & 7;        // A: 128 rows x 8 float4
    const int wrow0 = t >> 6, wc4 = t & 63 ? (t & 31) : 0; // placeholder (unused)

    auto fillA_direct = [&](int p, int kt) {
        #pragma unroll
        for (int i = 0; i < 4; i++) {
            int idx = t + 256 * i;
            int row = idx >> 3, c4 = idx & 7;
            float4 v = *(const float4*)&Ap[(size_t)(bm + row) * DM + kt * 32 + c4 * 4];
            float* d = sm + p * BUFWORDS + row * APITCH + c4 * 4;
            d[0] = __uint_as_float(f2tf32(v.x));
            d[1] = __uint_as_float(f2tf32(v.y));
            d[2] = __uint_as_float(f2tf32(v.z));
            d[3] = __uint_as_float(f2tf32(v.w));
        }
    };
    auto fillW_direct = [&](int p, int kt) {
        #pragma unroll
        for (int i = 0; i < 4; i++) {
            int idx = t + 256 * i;
            int row = idx >> 5, c4 = idx & 31;   // 32 rows x 32 float4
            float4 v = *(const float4*)&W[(size_t)(kt * 32 + row) * DM + bn + c4 * 4];
            float* d = sm + p * BUFWORDS + AWORDS + row * WPITCH + c4 * 4;
            d[0] = __uint_as_float(f2tf32(v.x));
            d[1] = __uint_as_float(f2tf32(v.y));
            d[2] = __uint_as_float(f2tf32(v.z));
            d[3] = __uint_as_float(f2tf32(v.w));
        }
    };

    fillA_direct(0, 0);
    fillW_direct(0, 0);
    __syncthreads();

    for (int kt = 0; kt < DM / 32; kt++) {
        const int p = kt & 1;

        // prefetch next tile into registers
        float4 pA[4], pW[4];
        if (kt + 1 < DM / 32) {
            #pragma unroll
            for (int i = 0; i < 4; i++) {
                int idx = t + 256 * i;
                int row = idx >> 3, c4 = idx & 7;
                pA[i] = *(const float4*)&Ap[(size_t)(bm + row) * DM + (kt + 1) * 32 + c4 * 4];
            }
            #pragma unroll
            for (int i = 0; i < 4; i++) {
                int idx = t + 256 * i;
                int row = idx >> 5, c4 = idx & 31;
                pW[i] = *(const float4*)&W[(size_t)((kt + 1) * 32 + row) * DM + bn + c4 * 4];
            }
        }

        // compute current buffer
        const float* As = sm + p * BUFWORDS;
        const float* Ws = sm + p * BUFWORDS + AWORDS;
        #pragma unroll
        for (int ks = 0; ks < 4; ks++) {
            const int k = ks * 8;
            uint32_t af[4][4];
            #pragma unroll
            for (int mt = 0; mt < 4; mt++) {
                const float* ab = As + (wr * 64 + mt * 16 + grp) * APITCH + k + qid;
                af[mt][0] = __float_as_uint(ab[0]);
                af[mt][1] = __float_as_uint(ab[8 * APITCH]);
                af[mt][2] = __float_as_uint(ab[4]);
                af[mt][3] = __float_as_uint(ab[8 * APITCH + 4]);
            }
            uint32_t bf[4][2];
            #pragma unroll
            for (int nt = 0; nt < 4; nt++) {
                const int cb = wc * 32 + nt * 8 + grp;
                bf[nt][0] = __float_as_uint(Ws[(k + qid) * WPITCH + cb]);
                bf[nt][1] = __float_as_uint(Ws[(k + qid + 4) * WPITCH + cb]);
            }
            #pragma unroll
            for (int mt = 0; mt < 4; mt++)
                #pragma unroll
                for (int nt = 0; nt < 4; nt++)
                    mma_tf32(c[mt][nt], af[mt][0], af[mt][1], af[mt][2], af[mt][3],
                             bf[nt][0], bf[nt][1]);
        }
        __syncthreads();

        // store prefetched tile
        if (kt + 1 < DM / 32) {
            const int np = (kt + 1) & 1;
            #pragma unroll
            for (int i = 0; i < 4; i++) {
                int idx = t + 256 * i;
                int row = idx >> 3, c4 = idx & 7;
                float* d = sm + np * BUFWORDS + row * APITCH + c4 * 4;
                d[0] = __uint_as_float(f2tf32(pA[i].x));
                d[1] = __uint_as_float(f2tf32(pA[i].y));
                d[2] = __uint_as_float(f2tf32(pA[i].z));
                d[3] = __uint_as_float(f2tf32(pA[i].w));
            }
            #pragma unroll
            for (int i = 0; i < 4; i++) {
                int idx = t + 256 * i;
                int row = idx >> 5, c4 = idx & 31;
                float* d = sm + np * BUFWORDS + AWORDS + row * WPITCH + c4 * 4;
                d[0] = __uint_as_float(f2tf32(pW[i].x));
                d[1] = __uint_as_float(f2tf32(pW[i].y));
                d[2] = __uint_as_float(f2tf32(pW[i].z));
                d[3] = __uint_as_float(f2tf32(pW[i].w));
            }
            __syncthreads();
        }
    }

    // epilogue: bias + scatter.  Fragment (mt,nt): rows r0/r0+8, cols 2*qid(+1)
    #pragma unroll
    for (int mt = 0; mt < 4; mt++) {
        #pragma unroll
        for (int nt = 0; nt < 4; nt++) {
            const int gc = bn + wc * 32 + nt * 8 + 2 * qid;
            const float bx = bias[gc], by = bias[gc + 1];
            #pragma unroll
            for (int half = 0; half < 2; half++) {
                const int gr = bm + wr * 64 + mt * 16 + grp + half * 8;
                float2 v;
                v.x = c[mt][nt][half * 2 + 0] + bx;
                v.y = c[mt][nt][half * 2 + 1] + by;
                if (MODE == 0) {
                    int b = gr >> 11, s = gr & (SEQ - 1);
                    int h = gc >> 6,  hd = gc & (HD - 1);
                    *(float2*)&dst[((size_t)((b * NH + h) * SEQ + s)) * HD + hd] = v;
                } else {
                    *(float2*)&dst[(size_t)gr * DM + gc] = v;
                }
            }
        }
    }
}

// ---------------------------------------------------------------------------
// Flash attention, fp32 (passing R2 version — next round's conversion target)
// ---------------------------------------------------------------------------
#define ATTN_SMEM_FLOATS (4096*3 + 1024*2)

__global__ void __launch_bounds__(256)
attn_kernel()
{
    extern __shared__ float sm[];
    float* QsT    = sm;
    float* KP     = sm + 4096;
    float* Vs     = sm + 8192;
    float* redmax = sm + 12288;
    float* redsum = sm + 13312;

    const int t  = threadIdx.x;
    const int tx = t & 15, ty = t >> 4;
    const int qt = blockIdx.x;
    const int bh = blockIdx.y;
    const int q0 = qt * 64;

    const float* Qg = g_q + ((size_t)bh * SEQ + q0) * HD;
    const float* Kg = g_k + (size_t)bh * SEQ * HD;
    const float* Vg = g_v + (size_t)bh * SEQ * HD;

    #pragma unroll
    for (int r = 0; r < 4; r++) {
        int lin = t + r * 256;
        int row = lin >> 4, d0 = (lin & 15) << 2;
        float4 v = *(const float4*)&Qg[row * HD + d0];
        QsT[(d0 + 0) * 64 + row] = v.x; QsT[(d0 + 1) * 64 + row] = v.y;
        QsT[(d0 + 2) * 64 + row] = v.z; QsT[(d0 + 3) * 64 + row] = v.w;
    }

    float o[4][4];
    float m[4], l[4];
    #pragma unroll
    for (int i = 0; i < 4; i++) {
        m[i] = -1e30f; l[i] = 0.f;
        #pragma unroll
        for (int j = 0; j < 4; j++) o[i][j] = 0.f;
    }

    const int ntiles = qt + 1;
    for (int kt = 0; kt < ntiles; kt++) {
        const int k0 = kt * 64;
        __syncthreads();
        #pragma unroll
        for (int r = 0; r < 4; r++) {
            int lin = t + r * 256;
            int row = lin >> 4, d0 = (lin & 15) << 2;
            float4 kv = *(const float4*)&Kg[(size_t)(k0 + row) * HD + d0];
            KP[(d0 + 0) * 64 + row] = kv.x; KP[(d0 + 1) * 64 + row] = kv.y;
            KP[(d0 + 2) * 64 + row] = kv.z; KP[(d0 + 3) * 64 + row] = kv.w;
            *(float4*)&Vs[row * HD + d0] =
                *(const float4*)&Vg[(size_t)(k0 + row) * HD + d0];
        }
        __syncthreads();

        float sacc[4][4];
        #pragma unroll
        for (int i = 0; i < 4; i++)
            #pragma unroll
            for (int j = 0; j < 4; j++) sacc[i][j] = 0.f;
        #pragma unroll 16
        for (int d = 0; d < 64; d++) {
            float4 qv = *(float4*)&QsT[d * 64 + ty * 4];
            float4 kv = *(float4*)&KP [d * 64 + tx * 4];
            float qa[4] = {qv.x, qv.y, qv.z, qv.w};
            float kb[4] = {kv.x, kv.y, kv.z, kv.w};
            #pragma unroll
            for (int i = 0; i < 4; i++)
                #pragma unroll
                for (int j = 0; j < 4; j++)
                    sacc[i][j] += qa[i] * kb[j];
        }

        float lm[4];
        #pragma unroll
        for (int i = 0; i < 4; i++) {
            int qg = q0 + ty * 4 + i;
            lm[i] = -1e30f;
            #pragma unroll
            for (int j = 0; j < 4; j++) {
                float s = sacc[i][j] * 0.125f;
                int kg = k0 + tx * 4 + j;
                if (kg > qg) s = -1e30f;
                sacc[i][j] = s;
                lm[i] = fmaxf(lm[i], s);
            }
            redmax[(ty * 4 + i) * 16 + tx] = lm[i];
        }
        __syncthreads();

        float mnew[4], corr[4];
        #pragma unroll
        for (int i = 0; i < 4; i++) {
            float rm = m[i];
            const float* rp = &redmax[(ty * 4 + i) * 16];
            #pragma unroll
            for (int c = 0; c < 16; c++) rm = fmaxf(rm, rp[c]);
            mnew[i] = rm;
            corr[i] = __expf(m[i] - rm);
            m[i] = rm;
        }
        #pragma unroll
        for (int i = 0; i < 4; i++) {
            float ls = 0.f;
            #pragma unroll
            for (int j = 0; j < 4; j++) {
                float p = __expf(sacc[i][j] - mnew[i]);
                sacc[i][j] = p;
                ls += p;
            }
            redsum[(ty * 4 + i) * 16 + tx] = ls;
            float4 pv = make_float4(sacc[i][0], sacc[i][1], sacc[i][2], sacc[i][3]);
            *(float4*)&KP[(ty * 4 + i) * 64 + tx * 4] = pv;
            #pragma unroll
            for (int j = 0; j < 4; j++) o[i][j] *= corr[i];
        }
        __syncthreads();

        #pragma unroll
        for (int i = 0; i < 4; i++) {
            float s2 = 0.f;
            const float* rp = &redsum[(ty * 4 + i) * 16];
            #pragma unroll
            for (int c = 0; c < 16; c++) s2 += rp[c];
            l[i] = l[i] * corr[i] + s2;
        }

        #pragma unroll 16
        for (int kk = 0; kk < 64; kk++) {
            float4 vv = *(float4*)&Vs[kk * 64 + tx * 4];
            float vb[4] = {vv.x, vv.y, vv.z, vv.w};
            float pv[4];
            #pragma unroll
            for (int i = 0; i < 4; i++)
                pv[i] = KP[(ty * 4 + i) * 64 + kk];
            #pragma unroll
            for (int i = 0; i < 4; i++)
                #pragma unroll
                for (int j = 0; j < 4; j++)
                    o[i][j] += pv[i] * vb[j];
        }
    }

    const int b = bh >> 4, h = bh & (NH - 1);
    #pragma unroll
    for (int i = 0; i < 4; i++) {
        float inv = 1.f / l[i];
        int s = q0 + ty * 4 + i;
        float4 v = make_float4(o[i][0] * inv, o[i][1] * inv,
                               o[i][2] * inv, o[i][3] * inv);
        *(float4*)&g_ao[((size_t)(b * SEQ + s)) * DM + h * HD + tx * 4] = v;
    }
}

// ---------------------------------------------------------------------------
extern "C" void kernel_launch(void* const* d_in, const int* in_sizes, int n_in,
                              void* d_out, int out_size)
{
    const float* x  = (const float*)d_in[0];
    const float* Wq = (const float*)d_in[1];
    const float* bq = (const float*)d_in[2];
    const float* Wk = (const float*)d_in[3];
    const float* bk = (const float*)d_in[4];
    const float* Wv = (const float*)d_in[5];
    const float* bv = (const float*)d_in[6];
    const float* Wo = (const float*)d_in[7];
    const float* bo = (const float*)d_in[8];

    cudaFuncSetAttribute(gemm_mma<0>,
                         cudaFuncAttributeMaxDynamicSharedMemorySize, GEMM_SMEM_BYTES);
    cudaFuncSetAttribute(gemm_mma<3>,
                         cudaFuncAttributeMaxDynamicSharedMemorySize, GEMM_SMEM_BYTES);

    gemm_mma<0><<<dim3(DM / 128, MTOT / 128, 3), 256, GEMM_SMEM_BYTES>>>(
        x, Wq, bq, Wk, bk, Wv, bv, nullptr);

    const int smem_bytes = ATTN_SMEM_FLOATS * (int)sizeof(float);
    cudaFuncSetAttribute(attn_kernel,
                         cudaFuncAttributeMaxDynamicSharedMemorySize, smem_bytes);
    attn_kernel<<<dim3(SEQ / 64, BATCH * NH), 256, smem_bytes>>>();

    gemm_mma<3><<<dim3(DM / 128, MTOT / 128, 1), 256, GEMM_SMEM_BYTES>>>(
        nullptr, Wo, bo, nullptr, nullptr, nullptr, nullptr, (float*)d_out);
}

// round 6
// speedup vs baseline: 2.8664x; 1.9590x over previous
#include <cuda_runtime.h>
#include <cstdint>

#define DM    1024
#define NH    16
#define HD    64
#define BATCH 2
#define SEQ   2048
#define MTOT  (BATCH*SEQ)   // 4096

// Scratch (allocation-free rule: __device__ globals)
__device__ float g_q [(long long)BATCH*NH*SEQ*HD];   // [b,h,s,hd]
__device__ float g_k [(long long)BATCH*NH*SEQ*HD];
__device__ float g_v [(long long)BATCH*NH*SEQ*HD];
__device__ float g_ao[(long long)MTOT*DM];           // [b,s,d]

__device__ __forceinline__ uint32_t f2tf32(float x) {
    uint32_t r;
    asm("cvt.rna.tf32.f32 %0, %1;" : "=r"(r) : "f"(x));
    return r;
}

__device__ __forceinline__ void mma_tf32(float c[4], uint32_t a0, uint32_t a1,
                                         uint32_t a2, uint32_t a3,
                                         uint32_t b0, uint32_t b1) {
    asm volatile(
        "mma.sync.aligned.m16n8k8.row.col.f32.tf32.tf32.f32 "
        "{%0,%1,%2,%3}, {%4,%5,%6,%7}, {%8,%9}, {%0,%1,%2,%3};"
        : "+f"(c[0]), "+f"(c[1]), "+f"(c[2]), "+f"(c[3])
        : "r"(a0), "r"(a1), "r"(a2), "r"(a3), "r"(b0), "r"(b1));
}

// ===========================================================================
// TF32 mma.sync GEMM (unchanged from R4 — passing at 280us for QKV)
// ===========================================================================
#define APITCH 36
#define WPITCH 132
#define AWORDS (128*APITCH)
#define WWORDS (32*WPITCH)
#define BUFWORDS (AWORDS + WWORDS)
#define GEMM_SMEM_BYTES (2*BUFWORDS*4)

template<int MODE>
__global__ void __launch_bounds__(256)
gemm_mma(const float* __restrict__ A0,
         const float* __restrict__ W0, const float* __restrict__ b0,
         const float* __restrict__ W1, const float* __restrict__ b1,
         const float* __restrict__ W2, const float* __restrict__ b2,
         float* __restrict__ Cout)
{
    extern __shared__ float sm[];

    const int t   = threadIdx.x;
    const int wid = t >> 5, lane = t & 31;
    const int grp = lane >> 2, qid = lane & 3;
    const int wr  = wid & 1, wc = wid >> 1;
    const int bn  = blockIdx.x * 128, bm = blockIdx.y * 128;

    const float* Ap;
    const float* W;
    const float* bias;
    float* dst;
    if (MODE == 3) {
        Ap = g_ao; W = W0; bias = b0; dst = Cout;
    } else {
        Ap = A0;
        int z = blockIdx.z;
        W    = (z == 0) ? W0 : (z == 1) ? W1 : W2;
        bias = (z == 0) ? b0 : (z == 1) ? b1 : b2;
        dst  = (z == 0) ? g_q : (z == 1) ? g_k : g_v;
    }

    float c[4][4][4];
    #pragma unroll
    for (int mt = 0; mt < 4; mt++)
        #pragma unroll
        for (int nt = 0; nt < 4; nt++)
            #pragma unroll
            for (int i = 0; i < 4; i++) c[mt][nt][i] = 0.f;

    auto fillA_direct = [&](int p, int kt) {
        #pragma unroll
        for (int i = 0; i < 4; i++) {
            int idx = t + 256 * i;
            int row = idx >> 3, c4 = idx & 7;
            float4 v = *(const float4*)&Ap[(size_t)(bm + row) * DM + kt * 32 + c4 * 4];
            float* d = sm + p * BUFWORDS + row * APITCH + c4 * 4;
            d[0] = __uint_as_float(f2tf32(v.x));
            d[1] = __uint_as_float(f2tf32(v.y));
            d[2] = __uint_as_float(f2tf32(v.z));
            d[3] = __uint_as_float(f2tf32(v.w));
        }
    };
    auto fillW_direct = [&](int p, int kt) {
        #pragma unroll
        for (int i = 0; i < 4; i++) {
            int idx = t + 256 * i;
            int row = idx >> 5, c4 = idx & 31;
            float4 v = *(const float4*)&W[(size_t)(kt * 32 + row) * DM + bn + c4 * 4];
            float* d = sm + p * BUFWORDS + AWORDS + row * WPITCH + c4 * 4;
            d[0] = __uint_as_float(f2tf32(v.x));
            d[1] = __uint_as_float(f2tf32(v.y));
            d[2] = __uint_as_float(f2tf32(v.z));
            d[3] = __uint_as_float(f2tf32(v.w));
        }
    };

    fillA_direct(0, 0);
    fillW_direct(0, 0);
    __syncthreads();

    for (int kt = 0; kt < DM / 32; kt++) {
        const int p = kt & 1;

        float4 pA[4], pW[4];
        if (kt + 1 < DM / 32) {
            #pragma unroll
            for (int i = 0; i < 4; i++) {
                int idx = t + 256 * i;
                int row = idx >> 3, c4 = idx & 7;
                pA[i] = *(const float4*)&Ap[(size_t)(bm + row) * DM + (kt + 1) * 32 + c4 * 4];
            }
            #pragma unroll
            for (int i = 0; i < 4; i++) {
                int idx = t + 256 * i;
                int row = idx >> 5, c4 = idx & 31;
                pW[i] = *(const float4*)&W[(size_t)((kt + 1) * 32 + row) * DM + bn + c4 * 4];
            }
        }

        const float* As = sm + p * BUFWORDS;
        const float* Ws = sm + p * BUFWORDS + AWORDS;
        #pragma unroll
        for (int ks = 0; ks < 4; ks++) {
            const int k = ks * 8;
            uint32_t af[4][4];
            #pragma unroll
            for (int mt = 0; mt < 4; mt++) {
                const float* ab = As + (wr * 64 + mt * 16 + grp) * APITCH + k + qid;
                af[mt][0] = __float_as_uint(ab[0]);
                af[mt][1] = __float_as_uint(ab[8 * APITCH]);
                af[mt][2] = __float_as_uint(ab[4]);
                af[mt][3] = __float_as_uint(ab[8 * APITCH + 4]);
            }
            uint32_t bf[4][2];
            #pragma unroll
            for (int nt = 0; nt < 4; nt++) {
                const int cb = wc * 32 + nt * 8 + grp;
                bf[nt][0] = __float_as_uint(Ws[(k + qid) * WPITCH + cb]);
                bf[nt][1] = __float_as_uint(Ws[(k + qid + 4) * WPITCH + cb]);
            }
            #pragma unroll
            for (int mt = 0; mt < 4; mt++)
                #pragma unroll
                for (int nt = 0; nt < 4; nt++)
                    mma_tf32(c[mt][nt], af[mt][0], af[mt][1], af[mt][2], af[mt][3],
                             bf[nt][0], bf[nt][1]);
        }
        __syncthreads();

        if (kt + 1 < DM / 32) {
            const int np = (kt + 1) & 1;
            #pragma unroll
            for (int i = 0; i < 4; i++) {
                int idx = t + 256 * i;
                int row = idx >> 3, c4 = idx & 7;
                float* d = sm + np * BUFWORDS + row * APITCH + c4 * 4;
                d[0] = __uint_as_float(f2tf32(pA[i].x));
                d[1] = __uint_as_float(f2tf32(pA[i].y));
                d[2] = __uint_as_float(f2tf32(pA[i].z));
                d[3] = __uint_as_float(f2tf32(pA[i].w));
            }
            #pragma unroll
            for (int i = 0; i < 4; i++) {
                int idx = t + 256 * i;
                int row = idx >> 5, c4 = idx & 31;
                float* d = sm + np * BUFWORDS + AWORDS + row * WPITCH + c4 * 4;
                d[0] = __uint_as_float(f2tf32(pW[i].x));
                d[1] = __uint_as_float(f2tf32(pW[i].y));
                d[2] = __uint_as_float(f2tf32(pW[i].z));
                d[3] = __uint_as_float(f2tf32(pW[i].w));
            }
            __syncthreads();
        }
    }

    #pragma unroll
    for (int mt = 0; mt < 4; mt++) {
        #pragma unroll
        for (int nt = 0; nt < 4; nt++) {
            const int gc = bn + wc * 32 + nt * 8 + 2 * qid;
            const float bx = bias[gc], by = bias[gc + 1];
            #pragma unroll
            for (int half = 0; half < 2; half++) {
                const int gr = bm + wr * 64 + mt * 16 + grp + half * 8;
                float2 v;
                v.x = c[mt][nt][half * 2 + 0] + bx;
                v.y = c[mt][nt][half * 2 + 1] + by;
                if (MODE == 0) {
                    int b = gr >> 11, s = gr & (SEQ - 1);
                    int h = gc >> 6,  hd = gc & (HD - 1);
                    *(float2*)&dst[((size_t)((b * NH + h) * SEQ + s)) * HD + hd] = v;
                } else {
                    *(float2*)&dst[(size_t)gr * DM + gc] = v;
                }
            }
        }
    }
}

// ===========================================================================
// TF32 mma.sync flash attention.
// BQ=BK=64, 128 threads = 4 warps, warp w owns Q-rows [w*16, w*16+16).
// S = Q@K^T (8 nt x 8 k-step mma), register softmax (quad shfl reductions),
// P staged tf32 through per-warp smem strip, PV mma into persistent O accs.
// grid: (SEQ/64, BATCH*NH)
// ===========================================================================
#define QPITCH 68
#define KPITCH 68
#define VPITCH 72
#define PPITCH 68
#define SM_Q 0
#define SM_K (SM_Q + 64*QPITCH)                 // 4352
#define SM_V (SM_K + 64*KPITCH)                 // 8704
#define SM_P (SM_V + 64*VPITCH)                 // 13312
#define ATTN_SMEM_WORDS (SM_P + 4*16*PPITCH)    // 17664
#define ATTN_SMEM_BYTES (ATTN_SMEM_WORDS*4)     // 70656

__global__ void __launch_bounds__(128)
attn_mma()
{
    extern __shared__ float sm[];

    const int t    = threadIdx.x;
    const int wid  = t >> 5, lane = t & 31;
    const int grp  = lane >> 2, qid = lane & 3;
    const int qt   = blockIdx.x;
    const int bh   = blockIdx.y;
    const int q0   = qt * 64;

    const float* Qg = g_q + ((size_t)bh * SEQ + q0) * HD;
    const float* Kg = g_k + (size_t)bh * SEQ * HD;
    const float* Vg = g_v + (size_t)bh * SEQ * HD;

    // Load Q tile (tf32-rounded), rows [64] x cols [64], pitch 68
    #pragma unroll
    for (int i = 0; i < 8; i++) {
        int idx = t + 128 * i;
        int row = idx >> 4, c4 = (idx & 15) << 2;
        float4 v = *(const float4*)&Qg[row * HD + c4];
        float* d = sm + SM_Q + row * QPITCH + c4;
        d[0] = __uint_as_float(f2tf32(v.x));
        d[1] = __uint_as_float(f2tf32(v.y));
        d[2] = __uint_as_float(f2tf32(v.z));
        d[3] = __uint_as_float(f2tf32(v.w));
    }

    float o[8][4];
    #pragma unroll
    for (int nt = 0; nt < 8; nt++)
        #pragma unroll
        for (int i = 0; i < 4; i++) o[nt][i] = 0.f;
    float m0 = -1e30f, m1 = -1e30f, l0 = 0.f, l1 = 0.f;

    float* Pw = sm + SM_P + wid * 16 * PPITCH;

    const int ntiles = qt + 1;
    for (int kt = 0; kt < ntiles; kt++) {
        const int k0 = kt * 64;
        __syncthreads();   // protect Ks/Vs reuse
        // Load K,V tiles (tf32-rounded)
        #pragma unroll
        for (int i = 0; i < 8; i++) {
            int idx = t + 128 * i;
            int row = idx >> 4, c4 = (idx & 15) << 2;
            float4 kv = *(const float4*)&Kg[(size_t)(k0 + row) * HD + c4];
            float* dk = sm + SM_K + row * KPITCH + c4;
            dk[0] = __uint_as_float(f2tf32(kv.x));
            dk[1] = __uint_as_float(f2tf32(kv.y));
            dk[2] = __uint_as_float(f2tf32(kv.z));
            dk[3] = __uint_as_float(f2tf32(kv.w));
            float4 vv = *(const float4*)&Vg[(size_t)(k0 + row) * HD + c4];
            float* dv = sm + SM_V + row * VPITCH + c4;
            dv[0] = __uint_as_float(f2tf32(vv.x));
            dv[1] = __uint_as_float(f2tf32(vv.y));
            dv[2] = __uint_as_float(f2tf32(vv.z));
            dv[3] = __uint_as_float(f2tf32(vv.w));
        }
        __syncthreads();

        // ---- S = Q @ K^T : warp rows [wid*16, +16), all 64 cols ----
        float s[8][4];
        #pragma unroll
        for (int nt = 0; nt < 8; nt++)
            #pragma unroll
            for (int i = 0; i < 4; i++) s[nt][i] = 0.f;

        const float* Qs = sm + SM_Q + (wid * 16) * QPITCH;
        const float* Ks = sm + SM_K;
        #pragma unroll
        for (int ks = 0; ks < 8; ks++) {
            const int k = ks * 8;
            uint32_t a0 = __float_as_uint(Qs[grp * QPITCH + k + qid]);
            uint32_t a1 = __float_as_uint(Qs[(grp + 8) * QPITCH + k + qid]);
            uint32_t a2 = __float_as_uint(Qs[grp * QPITCH + k + qid + 4]);
            uint32_t a3 = __float_as_uint(Qs[(grp + 8) * QPITCH + k + qid + 4]);
            #pragma unroll
            for (int nt = 0; nt < 8; nt++) {
                const int cb = nt * 8 + grp;
                uint32_t b0 = __float_as_uint(Ks[cb * KPITCH + k + qid]);
                uint32_t b1 = __float_as_uint(Ks[cb * KPITCH + k + qid + 4]);
                mma_tf32(s[nt], a0, a1, a2, a3, b0, b1);
            }
        }

        // ---- scale + causal mask (diagonal tile only) + row max ----
        const int r_lo = q0 + wid * 16 + grp;      // global row of c0/c1
        const int r_hi = r_lo + 8;                 // global row of c2/c3
        float lm0 = -1e30f, lm1 = -1e30f;
        #pragma unroll
        for (int nt = 0; nt < 8; nt++) {
            const int cg = k0 + nt * 8 + 2 * qid;
            #pragma unroll
            for (int i = 0; i < 4; i++) s[nt][i] *= 0.125f;
            if (kt == qt) {
                if (cg     > r_lo) s[nt][0] = -1e30f;
                if (cg + 1 > r_lo) s[nt][1] = -1e30f;
                if (cg     > r_hi) s[nt][2] = -1e30f;
                if (cg + 1 > r_hi) s[nt][3] = -1e30f;
            }
            lm0 = fmaxf(lm0, fmaxf(s[nt][0], s[nt][1]));
            lm1 = fmaxf(lm1, fmaxf(s[nt][2], s[nt][3]));
        }
        lm0 = fmaxf(lm0, __shfl_xor_sync(0xFFFFFFFFu, lm0, 1));
        lm0 = fmaxf(lm0, __shfl_xor_sync(0xFFFFFFFFu, lm0, 2));
        lm1 = fmaxf(lm1, __shfl_xor_sync(0xFFFFFFFFu, lm1, 1));
        lm1 = fmaxf(lm1, __shfl_xor_sync(0xFFFFFFFFu, lm1, 2));

        const float mn0 = fmaxf(m0, lm0), mn1 = fmaxf(m1, lm1);
        const float corr0 = __expf(m0 - mn0), corr1 = __expf(m1 - mn1);
        m0 = mn0; m1 = mn1;

        // ---- exp, row sums, stage P to smem (tf32-rounded) ----
        float ls0 = 0.f, ls1 = 0.f;
        #pragma unroll
        for (int nt = 0; nt < 8; nt++) {
            float p0 = __expf(s[nt][0] - mn0);
            float p1 = __expf(s[nt][1] - mn0);
            float p2 = __expf(s[nt][2] - mn1);
            float p3 = __expf(s[nt][3] - mn1);
            ls0 += p0 + p1; ls1 += p2 + p3;
            float2 vlo, vhi;
            vlo.x = __uint_as_float(f2tf32(p0));
            vlo.y = __uint_as_float(f2tf32(p1));
            vhi.x = __uint_as_float(f2tf32(p2));
            vhi.y = __uint_as_float(f2tf32(p3));
            *(float2*)&Pw[grp * PPITCH + nt * 8 + 2 * qid] = vlo;
            *(float2*)&Pw[(grp + 8) * PPITCH + nt * 8 + 2 * qid] = vhi;
        }
        ls0 += __shfl_xor_sync(0xFFFFFFFFu, ls0, 1);
        ls0 += __shfl_xor_sync(0xFFFFFFFFu, ls0, 2);
        ls1 += __shfl_xor_sync(0xFFFFFFFFu, ls1, 1);
        ls1 += __shfl_xor_sync(0xFFFFFFFFu, ls1, 2);
        l0 = l0 * corr0 + ls0;
        l1 = l1 * corr1 + ls1;

        // rescale O accumulators
        #pragma unroll
        for (int nt = 0; nt < 8; nt++) {
            o[nt][0] *= corr0; o[nt][1] *= corr0;
            o[nt][2] *= corr1; o[nt][3] *= corr1;
        }

        __syncwarp();   // P strip visible warp-wide

        // ---- O += P @ V ----
        const float* Vs = sm + SM_V;
        #pragma unroll
        for (int ks = 0; ks < 8; ks++) {
            const int k = ks * 8;
            uint32_t a0 = __float_as_uint(Pw[grp * PPITCH + k + qid]);
            uint32_t a1 = __float_as_uint(Pw[(grp + 8) * PPITCH + k + qid]);
            uint32_t a2 = __float_as_uint(Pw[grp * PPITCH + k + qid + 4]);
            uint32_t a3 = __float_as_uint(Pw[(grp + 8) * PPITCH + k + qid + 4]);
            #pragma unroll
            for (int nt = 0; nt < 8; nt++) {
                const int cb = nt * 8 + grp;
                uint32_t b0 = __float_as_uint(Vs[(k + qid) * VPITCH + cb]);
                uint32_t b1 = __float_as_uint(Vs[(k + qid + 4) * VPITCH + cb]);
                mma_tf32(o[nt], a0, a1, a2, a3, b0, b1);
            }
        }
        __syncwarp();   // P strip reads done before next tile's writes
    }

    // ---- epilogue: normalize, scatter to g_ao [b,s,d] ----
    const int b = bh >> 4, h = bh & (NH - 1);
    const float inv0 = 1.f / l0, inv1 = 1.f / l1;
    const int s_lo = q0 + wid * 16 + grp;
    const int s_hi = s_lo + 8;
    #pragma unroll
    for (int nt = 0; nt < 8; nt++) {
        const int col = h * HD + nt * 8 + 2 * qid;
        float2 vlo, vhi;
        vlo.x = o[nt][0] * inv0; vlo.y = o[nt][1] * inv0;
        vhi.x = o[nt][2] * inv1; vhi.y = o[nt][3] * inv1;
        *(float2*)&g_ao[((size_t)(b * SEQ + s_lo)) * DM + col] = vlo;
        *(float2*)&g_ao[((size_t)(b * SEQ + s_hi)) * DM + col] = vhi;
    }
}

// ---------------------------------------------------------------------------
extern "C" void kernel_launch(void* const* d_in, const int* in_sizes, int n_in,
                              void* d_out, int out_size)
{
    const float* x  = (const float*)d_in[0];
    const float* Wq = (const float*)d_in[1];
    const float* bq = (const float*)d_in[2];
    const float* Wk = (const float*)d_in[3];
    const float* bk = (const float*)d_in[4];
    const float* Wv = (const float*)d_in[5];
    const float* bv = (const float*)d_in[6];
    const float* Wo = (const float*)d_in[7];
    const float* bo = (const float*)d_in[8];

    cudaFuncSetAttribute(gemm_mma<0>,
                         cudaFuncAttributeMaxDynamicSharedMemorySize, GEMM_SMEM_BYTES);
    cudaFuncSetAttribute(gemm_mma<3>,
                         cudaFuncAttributeMaxDynamicSharedMemorySize, GEMM_SMEM_BYTES);
    cudaFuncSetAttribute(attn_mma,
                         cudaFuncAttributeMaxDynamicSharedMemorySize, ATTN_SMEM_BYTES);

    gemm_mma<0><<<dim3(DM / 128, MTOT / 128, 3), 256, GEMM_SMEM_BYTES>>>(
        x, Wq, bq, Wk, bk, Wv, bv, nullptr);

    attn_mma<<<dim3(SEQ / 64, BATCH * NH), 128, ATTN_SMEM_BYTES>>>();

    gemm_mma<3><<<dim3(DM / 128, MTOT / 128, 1), 256, GEMM_SMEM_BYTES>>>(
        nullptr, Wo, bo, nullptr, nullptr, nullptr, nullptr, (float*)d_out);
}

// round 9
// speedup vs baseline: 3.3981x; 1.1855x over previous
#include <cuda_runtime.h>
#include <cstdint>

#define DM    1024
#define NH    16
#define HD    64
#define BATCH 2
#define SEQ   2048
#define MTOT  (BATCH*SEQ)   // 4096

// Scratch (allocation-free rule: __device__ globals)
__device__ float g_q [(long long)BATCH*NH*SEQ*HD];   // [b,h,s,hd] tf32-rounded
__device__ float g_k [(long long)BATCH*NH*SEQ*HD];
__device__ float g_v [(long long)BATCH*NH*SEQ*HD];
__device__ float g_ao[(long long)MTOT*DM];           // [b,s,d]   tf32-rounded
__device__ float g_xc[(long long)MTOT*DM];           // x, tf32-rounded
__device__ float g_Wc[(long long)4*DM*DM];           // Wq|Wk|Wv|Wo, tf32-rounded

__device__ __forceinline__ uint32_t f2tf32(float x) {
    uint32_t r;
    asm("cvt.rna.tf32.f32 %0, %1;" : "=r"(r) : "f"(x));
    return r;
}

__device__ __forceinline__ uint32_t smem_u32(const void* p) {
    uint32_t a;
    asm("{ .reg .u64 t; cvta.to.shared.u64 t, %1; cvt.u32.u64 %0, t; }"
        : "=r"(a) : "l"(p));
    return a;
}

__device__ __forceinline__ void cp16(uint32_t dst, const void* src) {
    asm volatile("cp.async.cg.shared.global [%0], [%1], 16;"
                 :: "r"(dst), "l"(src) : "memory");
}
#define CP_COMMIT() asm volatile("cp.async.commit_group;" ::: "memory")
#define CP_WAIT(n)  asm volatile("cp.async.wait_group %0;" :: "n"(n) : "memory")

__device__ __forceinline__ void mma_tf32(float c[4], uint32_t a0, uint32_t a1,
                                         uint32_t a2, uint32_t a3,
                                         uint32_t b0, uint32_t b1) {
    asm volatile(
        "mma.sync.aligned.m16n8k8.row.col.f32.tf32.tf32.f32 "
        "{%0,%1,%2,%3}, {%4,%5,%6,%7}, {%8,%9}, {%0,%1,%2,%3};"
        : "+f"(c[0]), "+f"(c[1]), "+f"(c[2]), "+f"(c[3])
        : "r"(a0), "r"(a1), "r"(a2), "r"(a3), "r"(b0), "r"(b1));
}

// ===========================================================================
// Prep: tf32-round x and the 4 weight matrices into device scratch.
// ===========================================================================
#define NX4 (MTOT*DM/4)        // 1048576 float4
#define NW4 (DM*DM/4)          // 262144 float4

__global__ void __launch_bounds__(256)
prep_kernel(const float* __restrict__ x,
            const float* __restrict__ wq, const float* __restrict__ wk,
            const float* __restrict__ wv, const float* __restrict__ wo)
{
    const int i = blockIdx.x * blockDim.x + threadIdx.x;
    const float4* src;
    float4* dst;
    if (i < NX4) {
        src = (const float4*)x + i;
        dst = (float4*)g_xc + i;
    } else {
        int j = i - NX4;
        int w = j / NW4, r = j - w * NW4;
        const float* ws = (w == 0) ? wq : (w == 1) ? wk : (w == 2) ? wv : wo;
        src = (const float4*)ws + r;
        dst = (float4*)(g_Wc + (size_t)w * DM * DM) + r;
    }
    float4 v = *src;
    float4 o;
    o.x = __uint_as_float(f2tf32(v.x));
    o.y = __uint_as_float(f2tf32(v.y));
    o.z = __uint_as_float(f2tf32(v.z));
    o.w = __uint_as_float(f2tf32(v.w));
    *dst = o;
}

// ===========================================================================
// TF32 mma.sync GEMM, cp.async double-buffered.
// C[M,N] = A[M,1024] @ W[1024,N] + bias.  128x128 tile, 8 warps, 64x32/warp.
// MODE 0: A=g_xc, W=g_Wc[z], out=g_q/g_k/g_v (tf32-rounded, [b,h,s,hd])
// MODE 3: A=g_ao, W=g_Wc[3], out=d_out (full fp32, linear)
// ===========================================================================
#define APITCH 36
#define WPITCH 132
#define AWORDS (128*APITCH)
#define WWORDS (32*WPITCH)
#define BUFWORDS (AWORDS + WWORDS)
#define GEMM_SMEM_BYTES (2*BUFWORDS*4)
#define NKT (DM/32)

template<int MODE>
__global__ void __launch_bounds__(256, 2)
gemm_mma(const float* __restrict__ b0,
         const float* __restrict__ b1,
         const float* __restrict__ b2,
         float* __restrict__ Cout)
{
    extern __shared__ float sm[];
    const uint32_t sb = smem_u32(sm);

    const int t   = threadIdx.x;
    const int wid = t >> 5, lane = t & 31;
    const int grp = lane >> 2, qid = lane & 3;
    const int wr  = wid & 1, wc = wid >> 1;
    const int bn  = blockIdx.x * 128, bm = blockIdx.y * 128;

    const float* Ap;
    const float* W;
    const float* bias;
    float* dst;
    if (MODE == 3) {
        Ap = g_ao; W = g_Wc + (size_t)3 * DM * DM; bias = b0; dst = Cout;
    } else {
        Ap = g_xc;
        int z = blockIdx.z;
        W    = g_Wc + (size_t)z * DM * DM;
        bias = (z == 0) ? b0 : (z == 1) ? b1 : b2;
        dst  = (z == 0) ? g_q : (z == 1) ? g_k : g_v;
    }

    float c[4][4][4];
    #pragma unroll
    for (int mt = 0; mt < 4; mt++)
        #pragma unroll
        for (int nt = 0; nt < 4; nt++)
            #pragma unroll
            for (int i = 0; i < 4; i++) c[mt][nt][i] = 0.f;

    auto loadA = [&](int p, int kt) {
        #pragma unroll
        for (int i = 0; i < 4; i++) {
            int idx = t + 256 * i;
            int row = idx >> 3, c4 = idx & 7;
            cp16(sb + (uint32_t)(p * BUFWORDS + row * APITCH + c4 * 4) * 4,
                 &Ap[(size_t)(bm + row) * DM + kt * 32 + c4 * 4]);
        }
    };
    auto loadW = [&](int p, int kt) {
        #pragma unroll
        for (int i = 0; i < 4; i++) {
            int idx = t + 256 * i;
            int row = idx >> 5, c4 = idx & 31;
            cp16(sb + (uint32_t)(p * BUFWORDS + AWORDS + row * WPITCH + c4 * 4) * 4,
                 &W[(size_t)(kt * 32 + row) * DM + bn + c4 * 4]);
        }
    };

    loadA(0, 0); loadW(0, 0); CP_COMMIT();

    for (int kt = 0; kt < NKT; kt++) {
        const int p = kt & 1;
        if (kt + 1 < NKT) {
            loadA(p ^ 1, kt + 1); loadW(p ^ 1, kt + 1); CP_COMMIT();
            CP_WAIT(1);
        } else {
            CP_WAIT(0);
        }
        __syncthreads();

        const float* As = sm + p * BUFWORDS;
        const float* Ws = sm + p * BUFWORDS + AWORDS;
        #pragma unroll
        for (int ks = 0; ks < 4; ks++) {
            const int k = ks * 8;
            uint32_t af[4][4];
            #pragma unroll
            for (int mt = 0; mt < 4; mt++) {
                const float* ab = As + (wr * 64 + mt * 16 + grp) * APITCH + k + qid;
                af[mt][0] = __float_as_uint(ab[0]);
                af[mt][1] = __float_as_uint(ab[8 * APITCH]);
                af[mt][2] = __float_as_uint(ab[4]);
                af[mt][3] = __float_as_uint(ab[8 * APITCH + 4]);
            }
            uint32_t bf[4][2];
            #pragma unroll
            for (int nt = 0; nt < 4; nt++) {
                const int cb = wc * 32 + nt * 8 + grp;
                bf[nt][0] = __float_as_uint(Ws[(k + qid) * WPITCH + cb]);
                bf[nt][1] = __float_as_uint(Ws[(k + qid + 4) * WPITCH + cb]);
            }
            #pragma unroll
            for (int mt = 0; mt < 4; mt++)
                #pragma unroll
                for (int nt = 0; nt < 4; nt++)
                    mma_tf32(c[mt][nt], af[mt][0], af[mt][1], af[mt][2], af[mt][3],
                             bf[nt][0], bf[nt][1]);
        }
        __syncthreads();
    }

    #pragma unroll
    for (int mt = 0; mt < 4; mt++) {
        #pragma unroll
        for (int nt = 0; nt < 4; nt++) {
            const int gc = bn + wc * 32 + nt * 8 + 2 * qid;
            const float bx = bias[gc], by = bias[gc + 1];
            #pragma unroll
            for (int half = 0; half < 2; half++) {
                const int gr = bm + wr * 64 + mt * 16 + grp + half * 8;
                float2 v;
                if (MODE == 0) {
                    // round for the tf32 attention consumers
                    v.x = __uint_as_float(f2tf32(c[mt][nt][half * 2 + 0] + bx));
                    v.y = __uint_as_float(f2tf32(c[mt][nt][half * 2 + 1] + by));
                    int b = gr >> 11, s = gr & (SEQ - 1);
                    int h = gc >> 6,  hd = gc & (HD - 1);
                    *(float2*)&dst[((size_t)((b * NH + h) * SEQ + s)) * HD + hd] = v;
                } else {
                    v.x = c[mt][nt][half * 2 + 0] + bx;
                    v.y = c[mt][nt][half * 2 + 1] + by;
                    *(float2*)&dst[(size_t)gr * DM + gc] = v;
                }
            }
        }
    }
}

// ===========================================================================
// TF32 mma.sync flash attention, cp.async double-buffered K/V.
// BQ=BK=64, 128 threads = 4 warps. Inputs already tf32-rounded.
// grid: (SEQ/64, BATCH*NH); q-tiles reversed so long blocks start first.
// ===========================================================================
#define QPITCH 68
#define KPITCH 68
#define VPITCH 72
#define PPITCH 68
#define SM_Q   0
#define SM_KV0 (64*QPITCH)                       // 4352
#define KVWORDS (64*KPITCH + 64*VPITCH)          // 8960 per stage
#define SM_P   (SM_KV0 + 2*KVWORDS)              // 22272
#define ATTN_SMEM_WORDS (SM_P + 4*16*PPITCH)     // 26624
#define ATTN_SMEM_BYTES (ATTN_SMEM_WORDS*4)      // 106496

__global__ void __launch_bounds__(128)
attn_mma()
{
    extern __shared__ float sm[];
    const uint32_t sb = smem_u32(sm);

    const int t    = threadIdx.x;
    const int wid  = t >> 5, lane = t & 31;
    const int grp  = lane >> 2, qid = lane & 3;
    const int qt   = gridDim.x - 1 - blockIdx.x;   // longest blocks first
    const int bh   = blockIdx.y;
    const int q0   = qt * 64;

    const float* Qg = g_q + ((size_t)bh * SEQ + q0) * HD;
    const float* Kg = g_k + (size_t)bh * SEQ * HD;
    const float* Vg = g_v + (size_t)bh * SEQ * HD;

    auto loadKV = [&](int p, int kt) {
        const int k0 = kt * 64;
        const uint32_t kb = sb + (uint32_t)(SM_KV0 + p * KVWORDS) * 4;
        #pragma unroll
        for (int i = 0; i < 8; i++) {
            int idx = t + 128 * i;
            int row = idx >> 4, c4 = (idx & 15) << 2;
            cp16(kb + (uint32_t)(row * KPITCH + c4) * 4,
                 &Kg[(size_t)(k0 + row) * HD + c4]);
            cp16(kb + (uint32_t)(64 * KPITCH + row * VPITCH + c4) * 4,
                 &Vg[(size_t)(k0 + row) * HD + c4]);
        }
    };

    // Q tile + first K/V stage in one group
    #pragma unroll
    for (int i = 0; i < 8; i++) {
        int idx = t + 128 * i;
        int row = idx >> 4, c4 = (idx & 15) << 2;
        cp16(sb + (uint32_t)(SM_Q + row * QPITCH + c4) * 4,
             &Qg[(size_t)row * HD + c4]);
    }
    loadKV(0, 0);
    CP_COMMIT();

    float o[8][4];
    #pragma unroll
    for (int nt = 0; nt < 8; nt++)
        #pragma unroll
        for (int i = 0; i < 4; i++) o[nt][i] = 0.f;
    float m0 = -1e30f, m1 = -1e30f, l0 = 0.f, l1 = 0.f;

    float* Pw = sm + SM_P + wid * 16 * PPITCH;

    const int ntiles = qt + 1;
    for (int kt = 0; kt < ntiles; kt++) {
        const int p = kt & 1;
        if (kt + 1 < ntiles) {
            loadKV(p ^ 1, kt + 1); CP_COMMIT();
            CP_WAIT(1);
        } else {
            CP_WAIT(0);
        }
        __syncthreads();

        const int k0 = kt * 64;
        const float* Ks = sm + SM_KV0 + p * KVWORDS;
        const float* Vs = Ks + 64 * KPITCH;

        // ---- S = Q @ K^T ----
        float s[8][4];
        #pragma unroll
        for (int nt = 0; nt < 8; nt++)
            #pragma unroll
            for (int i = 0; i < 4; i++) s[nt][i] = 0.f;

        const float* Qs = sm + SM_Q + (wid * 16) * QPITCH;
        #pragma unroll
        for (int ks = 0; ks < 8; ks++) {
            const int k = ks * 8;
            uint32_t a0 = __float_as_uint(Qs[grp * QPITCH + k + qid]);
            uint32_t a1 = __float_as_uint(Qs[(grp + 8) * QPITCH + k + qid]);
            uint32_t a2 = __float_as_uint(Qs[grp * QPITCH + k + qid + 4]);
            uint32_t a3 = __float_as_uint(Qs[(grp + 8) * QPITCH + k + qid + 4]);
            #pragma unroll
            for (int nt = 0; nt < 8; nt++) {
                const int cb = nt * 8 + grp;
                uint32_t b0 = __float_as_uint(Ks[cb * KPITCH + k + qid]);
                uint32_t b1 = __float_as_uint(Ks[cb * KPITCH + k + qid + 4]);
                mma_tf32(s[nt], a0, a1, a2, a3, b0, b1);
            }
        }

        // ---- scale + causal mask (diagonal tile only) + row max ----
        const int r_lo = q0 + wid * 16 + grp;
        const int r_hi = r_lo + 8;
        float lm0 = -1e30f, lm1 = -1e30f;
        #pragma unroll
        for (int nt = 0; nt < 8; nt++) {
            const int cg = k0 + nt * 8 + 2 * qid;
            #pragma unroll
            for (int i = 0; i < 4; i++) s[nt][i] *= 0.125f;
            if (kt == ntiles - 1) {   // diagonal tile (kt == qt)
                if (cg     > r_lo) s[nt][0] = -1e30f;
                if (cg + 1 > r_lo) s[nt][1] = -1e30f;
                if (cg     > r_hi) s[nt][2] = -1e30f;
                if (cg + 1 > r_hi) s[nt][3] = -1e30f;
            }
            lm0 = fmaxf(lm0, fmaxf(s[nt][0], s[nt][1]));
            lm1 = fmaxf(lm1, fmaxf(s[nt][2], s[nt][3]));
        }
        lm0 = fmaxf(lm0, __shfl_xor_sync(0xFFFFFFFFu, lm0, 1));
        lm0 = fmaxf(lm0, __shfl_xor_sync(0xFFFFFFFFu, lm0, 2));
        lm1 = fmaxf(lm1, __shfl_xor_sync(0xFFFFFFFFu, lm1, 1));
        lm1 = fmaxf(lm1, __shfl_xor_sync(0xFFFFFFFFu, lm1, 2));

        const float mn0 = fmaxf(m0, lm0), mn1 = fmaxf(m1, lm1);
        const float corr0 = __expf(m0 - mn0), corr1 = __expf(m1 - mn1);
        m0 = mn0; m1 = mn1;

        // ---- exp, row sums, stage P (tf32) ----
        float ls0 = 0.f, ls1 = 0.f;
        #pragma unroll
        for (int nt = 0; nt < 8; nt++) {
            float p0 = __expf(s[nt][0] - mn0);
            float p1 = __expf(s[nt][1] - mn0);
            float p2 = __expf(s[nt][2] - mn1);
            float p3 = __expf(s[nt][3] - mn1);
            ls0 += p0 + p1; ls1 += p2 + p3;
            float2 vlo, vhi;
            vlo.x = __uint_as_float(f2tf32(p0));
            vlo.y = __uint_as_float(f2tf32(p1));
            vhi.x = __uint_as_float(f2tf32(p2));
            vhi.y = __uint_as_float(f2tf32(p3));
            *(float2*)&Pw[grp * PPITCH + nt * 8 + 2 * qid] = vlo;
            *(float2*)&Pw[(grp + 8) * PPITCH + nt * 8 + 2 * qid] = vhi;
        }
        ls0 += __shfl_xor_sync(0xFFFFFFFFu, ls0, 1);
        ls0 += __shfl_xor_sync(0xFFFFFFFFu, ls0, 2);
        ls1 += __shfl_xor_sync(0xFFFFFFFFu, ls1, 1);
        ls1 += __shfl_xor_sync(0xFFFFFFFFu, ls1, 2);
        l0 = l0 * corr0 + ls0;
        l1 = l1 * corr1 + ls1;

        #pragma unroll
        for (int nt = 0; nt < 8; nt++) {
            o[nt][0] *= corr0; o[nt][1] *= corr0;
            o[nt][2] *= corr1; o[nt][3] *= corr1;
        }

        __syncwarp();

        // ---- O += P @ V ----
        #pragma unroll
        for (int ks = 0; ks < 8; ks++) {
            const int k = ks * 8;
            uint32_t a0 = __float_as_uint(Pw[grp * PPITCH + k + qid]);
            uint32_t a1 = __float_as_uint(Pw[(grp + 8) * PPITCH + k + qid]);
            uint32_t a2 = __float_as_uint(Pw[grp * PPITCH + k + qid + 4]);
            uint32_t a3 = __float_as_uint(Pw[(grp + 8) * PPITCH + k + qid + 4]);
            #pragma unroll
            for (int nt = 0; nt < 8; nt++) {
                const int cb = nt * 8 + grp;
                uint32_t b0 = __float_as_uint(Vs[(k + qid) * VPITCH + cb]);
                uint32_t b1 = __float_as_uint(Vs[(k + qid + 4) * VPITCH + cb]);
                mma_tf32(o[nt], a0, a1, a2, a3, b0, b1);
            }
        }
        __syncthreads();   // stage p free for reuse; P strip reads done
    }

    // ---- epilogue: normalize, tf32-round (for O-proj), scatter ----
    const int b = bh >> 4, h = bh & (NH - 1);
    const float inv0 = 1.f / l0, inv1 = 1.f / l1;
    const int s_lo = q0 + wid * 16 + grp;
    const int s_hi = s_lo + 8;
    #pragma unroll
    for (int nt = 0; nt < 8; nt++) {
        const int col = h * HD + nt * 8 + 2 * qid;
        float2 vlo, vhi;
        vlo.x = __uint_as_float(f2tf32(o[nt][0] * inv0));
        vlo.y = __uint_as_float(f2tf32(o[nt][1] * inv0));
        vhi.x = __uint_as_float(f2tf32(o[nt][2] * inv1));
        vhi.y = __uint_as_float(f2tf32(o[nt][3] * inv1));
        *(float2*)&g_ao[((size_t)(b * SEQ + s_lo)) * DM + col] = vlo;
        *(float2*)&g_ao[((size_t)(b * SEQ + s_hi)) * DM + col] = vhi;
    }
}

// ---------------------------------------------------------------------------
extern "C" void kernel_launch(void* const* d_in, const int* in_sizes, int n_in,
                              void* d_out, int out_size)
{
    const float* x  = (const float*)d_in[0];
    const float* Wq = (const float*)d_in[1];
    const float* bq = (const float*)d_in[2];
    const float* Wk = (const float*)d_in[3];
    const float* bk = (const float*)d_in[4];
    const float* Wv = (const float*)d_in[5];
    const float* bv = (const float*)d_in[6];
    const float* Wo = (const float*)d_in[7];
    const float* bo = (const float*)d_in[8];

    cudaFuncSetAttribute(gemm_mma<0>,
                         cudaFuncAttributeMaxDynamicSharedMemorySize, GEMM_SMEM_BYTES);
    cudaFuncSetAttribute(gemm_mma<3>,
                         cudaFuncAttributeMaxDynamicSharedMemorySize, GEMM_SMEM_BYTES);
    cudaFuncSetAttribute(attn_mma,
                         cudaFuncAttributeMaxDynamicSharedMemorySize, ATTN_SMEM_BYTES);

    prep_kernel<<<(NX4 + 4 * NW4) / 256, 256>>>(x, Wq, Wk, Wv, Wo);

    gemm_mma<0><<<dim3(DM / 128, MTOT / 128, 3), 256, GEMM_SMEM_BYTES>>>(
        bq, bk, bv, nullptr);

    attn_mma<<<dim3(SEQ / 64, BATCH * NH), 128, ATTN_SMEM_BYTES>>>();

    gemm_mma<3><<<dim3(DM / 128, MTOT / 128, 1), 256, GEMM_SMEM_BYTES>>>(
        bo, nullptr, nullptr, (float*)d_out);
}

// round 10
// speedup vs baseline: 3.5311x; 1.0391x over previous
#include <cuda_runtime.h>
#include <cstdint>

#define DM    1024
#define NH    16
#define HD    64
#define BATCH 2
#define SEQ   2048
#define MTOT  (BATCH*SEQ)   // 4096

// Scratch (allocation-free rule: __device__ globals)
__device__ float g_q [(long long)BATCH*NH*SEQ*HD];   // [b,h,s,hd] tf32-rounded
__device__ float g_k [(long long)BATCH*NH*SEQ*HD];
__device__ float g_v [(long long)BATCH*NH*SEQ*HD];
__device__ float g_ao[(long long)MTOT*DM];           // [b,s,d]   tf32-rounded
__device__ float g_xc[(long long)MTOT*DM];           // x, tf32-rounded
__device__ float g_Wc[(long long)4*DM*DM];           // Wq|Wk|Wv|Wo, tf32-rounded

__device__ __forceinline__ uint32_t f2tf32(float x) {
    uint32_t r;
    asm("cvt.rna.tf32.f32 %0, %1;" : "=r"(r) : "f"(x));
    return r;
}

__device__ __forceinline__ uint32_t smem_u32(const void* p) {
    uint32_t a;
    asm("{ .reg .u64 t; cvta.to.shared.u64 t, %1; cvt.u32.u64 %0, t; }"
        : "=r"(a) : "l"(p));
    return a;
}

__device__ __forceinline__ void cp16(uint32_t dst, const void* src) {
    asm volatile("cp.async.cg.shared.global [%0], [%1], 16;"
                 :: "r"(dst), "l"(src) : "memory");
}
#define CP_COMMIT() asm volatile("cp.async.commit_group;" ::: "memory")
#define CP_WAIT(n)  asm volatile("cp.async.wait_group %0;" :: "n"(n) : "memory")

__device__ __forceinline__ void mma_tf32(float c[4], uint32_t a0, uint32_t a1,
                                         uint32_t a2, uint32_t a3,
                                         uint32_t b0, uint32_t b1) {
    asm volatile(
        "mma.sync.aligned.m16n8k8.row.col.f32.tf32.tf32.f32 "
        "{%0,%1,%2,%3}, {%4,%5,%6,%7}, {%8,%9}, {%0,%1,%2,%3};"
        : "+f"(c[0]), "+f"(c[1]), "+f"(c[2]), "+f"(c[3])
        : "r"(a0), "r"(a1), "r"(a2), "r"(a3), "r"(b0), "r"(b1));
}

// ===========================================================================
// Prep: tf32-round x and the 4 weight matrices into device scratch.
// ===========================================================================
#define NX4 (MTOT*DM/4)        // 1048576 float4
#define NW4 (DM*DM/4)          // 262144 float4

__global__ void __launch_bounds__(256)
prep_kernel(const float* __restrict__ x,
            const float* __restrict__ wq, const float* __restrict__ wk,
            const float* __restrict__ wv, const float* __restrict__ wo)
{
    const int i = blockIdx.x * blockDim.x + threadIdx.x;
    const float4* src;
    float4* dst;
    if (i < NX4) {
        src = (const float4*)x + i;
        dst = (float4*)g_xc + i;
    } else {
        int j = i - NX4;
        int w = j / NW4, r = j - w * NW4;
        const float* ws = (w == 0) ? wq : (w == 1) ? wk : (w == 2) ? wv : wo;
        src = (const float4*)ws + r;
        dst = (float4*)(g_Wc + (size_t)w * DM * DM) + r;
    }
    float4 v = *src;
    float4 o;
    o.x = __uint_as_float(f2tf32(v.x));
    o.y = __uint_as_float(f2tf32(v.y));
    o.z = __uint_as_float(f2tf32(v.z));
    o.w = __uint_as_float(f2tf32(v.w));
    *dst = o;
}

// ===========================================================================
// TF32 mma.sync GEMM, 3-stage cp.async pipeline, ONE barrier per K-iter.
// C[M,N] = A[M,1024] @ W[1024,N] + bias.  128x128 tile, 8 warps, 64x32/warp.
// MODE 0: A=g_xc, W=g_Wc[z], out=g_q/g_k/g_v (tf32-rounded, [b,h,s,hd])
// MODE 3: A=g_ao, W=g_Wc[3], out=d_out (full fp32, linear)
// ===========================================================================
#define APITCH 36
#define WPITCH 132
#define AWORDS (128*APITCH)
#define WWORDS (32*WPITCH)
#define BUFWORDS (AWORDS + WWORDS)          // 8832 words per stage
#define NSTAGE 3
#define GEMM_SMEM_BYTES (NSTAGE*BUFWORDS*4) // 105984
#define NKT (DM/32)

template<int MODE>
__global__ void __launch_bounds__(256, 2)
gemm_mma(const float* __restrict__ b0,
         const float* __restrict__ b1,
         const float* __restrict__ b2,
         float* __restrict__ Cout)
{
    extern __shared__ float sm[];
    const uint32_t sb = smem_u32(sm);

    const int t   = threadIdx.x;
    const int wid = t >> 5, lane = t & 31;
    const int grp = lane >> 2, qid = lane & 3;
    const int wr  = wid & 1, wc = wid >> 1;
    const int bn  = blockIdx.x * 128, bm = blockIdx.y * 128;

    const float* Ap;
    const float* W;
    const float* bias;
    float* dst;
    if (MODE == 3) {
        Ap = g_ao; W = g_Wc + (size_t)3 * DM * DM; bias = b0; dst = Cout;
    } else {
        Ap = g_xc;
        int z = blockIdx.z;
        W    = g_Wc + (size_t)z * DM * DM;
        bias = (z == 0) ? b0 : (z == 1) ? b1 : b2;
        dst  = (z == 0) ? g_q : (z == 1) ? g_k : g_v;
    }

    float c[4][4][4];
    #pragma unroll
    for (int mt = 0; mt < 4; mt++)
        #pragma unroll
        for (int nt = 0; nt < 4; nt++)
            #pragma unroll
            for (int i = 0; i < 4; i++) c[mt][nt][i] = 0.f;

    auto loadA = [&](int p, int kt) {
        #pragma unroll
        for (int i = 0; i < 4; i++) {
            int idx = t + 256 * i;
            int row = idx >> 3, c4 = idx & 7;
            cp16(sb + (uint32_t)(p * BUFWORDS + row * APITCH + c4 * 4) * 4,
                 &Ap[(size_t)(bm + row) * DM + kt * 32 + c4 * 4]);
        }
    };
    auto loadW = [&](int p, int kt) {
        #pragma unroll
        for (int i = 0; i < 4; i++) {
            int idx = t + 256 * i;
            int row = idx >> 5, c4 = idx & 31;
            cp16(sb + (uint32_t)(p * BUFWORDS + AWORDS + row * WPITCH + c4 * 4) * 4,
                 &W[(size_t)(kt * 32 + row) * DM + bn + c4 * 4]);
        }
    };

    // prologue: stages 0 and 1 in flight
    loadA(0, 0); loadW(0, 0); CP_COMMIT();
    loadA(1, 1); loadW(1, 1); CP_COMMIT();

    int cs = 0;      // compute stage
    int ls = 2;      // stage to load into next
    for (int kt = 0; kt < NKT; kt++) {
        if (kt + 1 < NKT) { CP_WAIT(1); } else { CP_WAIT(0); }
        __syncthreads();   // stage cs visible to all; all warps done with stage ls

        if (kt + 2 < NKT) {
            loadA(ls, kt + 2); loadW(ls, kt + 2); CP_COMMIT();
            ls = (ls + 1 == NSTAGE) ? 0 : ls + 1;
        }

        const float* As = sm + cs * BUFWORDS;
        const float* Ws = sm + cs * BUFWORDS + AWORDS;
        #pragma unroll
        for (int ks = 0; ks < 4; ks++) {
            const int k = ks * 8;
            uint32_t af[4][4];
            #pragma unroll
            for (int mt = 0; mt < 4; mt++) {
                const float* ab = As + (wr * 64 + mt * 16 + grp) * APITCH + k + qid;
                af[mt][0] = __float_as_uint(ab[0]);
                af[mt][1] = __float_as_uint(ab[8 * APITCH]);
                af[mt][2] = __float_as_uint(ab[4]);
                af[mt][3] = __float_as_uint(ab[8 * APITCH + 4]);
            }
            uint32_t bf[4][2];
            #pragma unroll
            for (int nt = 0; nt < 4; nt++) {
                const int cb = wc * 32 + nt * 8 + grp;
                bf[nt][0] = __float_as_uint(Ws[(k + qid) * WPITCH + cb]);
                bf[nt][1] = __float_as_uint(Ws[(k + qid + 4) * WPITCH + cb]);
            }
            #pragma unroll
            for (int mt = 0; mt < 4; mt++)
                #pragma unroll
                for (int nt = 0; nt < 4; nt++)
                    mma_tf32(c[mt][nt], af[mt][0], af[mt][1], af[mt][2], af[mt][3],
                             bf[nt][0], bf[nt][1]);
        }
        cs = (cs + 1 == NSTAGE) ? 0 : cs + 1;
    }

    #pragma unroll
    for (int mt = 0; mt < 4; mt++) {
        #pragma unroll
        for (int nt = 0; nt < 4; nt++) {
            const int gc = bn + wc * 32 + nt * 8 + 2 * qid;
            const float bx = bias[gc], by = bias[gc + 1];
            #pragma unroll
            for (int half = 0; half < 2; half++) {
                const int gr = bm + wr * 64 + mt * 16 + grp + half * 8;
                float2 v;
                if (MODE == 0) {
                    // round for the tf32 attention consumers
                    v.x = __uint_as_float(f2tf32(c[mt][nt][half * 2 + 0] + bx));
                    v.y = __uint_as_float(f2tf32(c[mt][nt][half * 2 + 1] + by));
                    int b = gr >> 11, s = gr & (SEQ - 1);
                    int h = gc >> 6,  hd = gc & (HD - 1);
                    *(float2*)&dst[((size_t)((b * NH + h) * SEQ + s)) * HD + hd] = v;
                } else {
                    v.x = c[mt][nt][half * 2 + 0] + bx;
                    v.y = c[mt][nt][half * 2 + 1] + by;
                    *(float2*)&dst[(size_t)gr * DM + gc] = v;
                }
            }
        }
    }
}

// ===========================================================================
// TF32 mma.sync flash attention, cp.async double-buffered K/V.
// (unchanged from R9 — passing; next measurement target)
// ===========================================================================
#define QPITCH 68
#define KPITCH 68
#define VPITCH 72
#define PPITCH 68
#define SM_Q   0
#define SM_KV0 (64*QPITCH)                       // 4352
#define KVWORDS (64*KPITCH + 64*VPITCH)          // 8960 per stage
#define SM_P   (SM_KV0 + 2*KVWORDS)              // 22272
#define ATTN_SMEM_WORDS (SM_P + 4*16*PPITCH)     // 26624
#define ATTN_SMEM_BYTES (ATTN_SMEM_WORDS*4)      // 106496

__global__ void __launch_bounds__(128)
attn_mma()
{
    extern __shared__ float sm[];
    const uint32_t sb = smem_u32(sm);

    const int t    = threadIdx.x;
    const int wid  = t >> 5, lane = t & 31;
    const int grp  = lane >> 2, qid = lane & 3;
    const int qt   = gridDim.x - 1 - blockIdx.x;   // longest blocks first
    const int bh   = blockIdx.y;
    const int q0   = qt * 64;

    const float* Qg = g_q + ((size_t)bh * SEQ + q0) * HD;
    const float* Kg = g_k + (size_t)bh * SEQ * HD;
    const float* Vg = g_v + (size_t)bh * SEQ * HD;

    auto loadKV = [&](int p, int kt) {
        const int k0 = kt * 64;
        const uint32_t kb = sb + (uint32_t)(SM_KV0 + p * KVWORDS) * 4;
        #pragma unroll
        for (int i = 0; i < 8; i++) {
            int idx = t + 128 * i;
            int row = idx >> 4, c4 = (idx & 15) << 2;
            cp16(kb + (uint32_t)(row * KPITCH + c4) * 4,
                 &Kg[(size_t)(k0 + row) * HD + c4]);
            cp16(kb + (uint32_t)(64 * KPITCH + row * VPITCH + c4) * 4,
                 &Vg[(size_t)(k0 + row) * HD + c4]);
        }
    };

    // Q tile + first K/V stage in one group
    #pragma unroll
    for (int i = 0; i < 8; i++) {
        int idx = t + 128 * i;
        int row = idx >> 4, c4 = (idx & 15) << 2;
        cp16(sb + (uint32_t)(SM_Q + row * QPITCH + c4) * 4,
             &Qg[(size_t)row * HD + c4]);
    }
    loadKV(0, 0);
    CP_COMMIT();

    float o[8][4];
    #pragma unroll
    for (int nt = 0; nt < 8; nt++)
        #pragma unroll
        for (int i = 0; i < 4; i++) o[nt][i] = 0.f;
    float m0 = -1e30f, m1 = -1e30f, l0 = 0.f, l1 = 0.f;

    float* Pw = sm + SM_P + wid * 16 * PPITCH;

    const int ntiles = qt + 1;
    for (int kt = 0; kt < ntiles; kt++) {
        const int p = kt & 1;
        if (kt + 1 < ntiles) {
            loadKV(p ^ 1, kt + 1); CP_COMMIT();
            CP_WAIT(1);
        } else {
            CP_WAIT(0);
        }
        __syncthreads();

        const int k0 = kt * 64;
        const float* Ks = sm + SM_KV0 + p * KVWORDS;
        const float* Vs = Ks + 64 * KPITCH;

        // ---- S = Q @ K^T ----
        float s[8][4];
        #pragma unroll
        for (int nt = 0; nt < 8; nt++)
            #pragma unroll
            for (int i = 0; i < 4; i++) s[nt][i] = 0.f;

        const float* Qs = sm + SM_Q + (wid * 16) * QPITCH;
        #pragma unroll
        for (int ks = 0; ks < 8; ks++) {
            const int k = ks * 8;
            uint32_t a0 = __float_as_uint(Qs[grp * QPITCH + k + qid]);
            uint32_t a1 = __float_as_uint(Qs[(grp + 8) * QPITCH + k + qid]);
            uint32_t a2 = __float_as_uint(Qs[grp * QPITCH + k + qid + 4]);
            uint32_t a3 = __float_as_uint(Qs[(grp + 8) * QPITCH + k + qid + 4]);
            #pragma unroll
            for (int nt = 0; nt < 8; nt++) {
                const int cb = nt * 8 + grp;
                uint32_t b0 = __float_as_uint(Ks[cb * KPITCH + k + qid]);
                uint32_t b1 = __float_as_uint(Ks[cb * KPITCH + k + qid + 4]);
                mma_tf32(s[nt], a0, a1, a2, a3, b0, b1);
            }
        }

        // ---- scale + causal mask (diagonal tile only) + row max ----
        const int r_lo = q0 + wid * 16 + grp;
        const int r_hi = r_lo + 8;
        float lm0 = -1e30f, lm1 = -1e30f;
        #pragma unroll
        for (int nt = 0; nt < 8; nt++) {
            const int cg = k0 + nt * 8 + 2 * qid;
            #pragma unroll
            for (int i = 0; i < 4; i++) s[nt][i] *= 0.125f;
            if (kt == ntiles - 1) {   // diagonal tile (kt == qt)
                if (cg     > r_lo) s[nt][0] = -1e30f;
                if (cg + 1 > r_lo) s[nt][1] = -1e30f;
                if (cg     > r_hi) s[nt][2] = -1e30f;
                if (cg + 1 > r_hi) s[nt][3] = -1e30f;
            }
            lm0 = fmaxf(lm0, fmaxf(s[nt][0], s[nt][1]));
            lm1 = fmaxf(lm1, fmaxf(s[nt][2], s[nt][3]));
        }
        lm0 = fmaxf(lm0, __shfl_xor_sync(0xFFFFFFFFu, lm0, 1));
        lm0 = fmaxf(lm0, __shfl_xor_sync(0xFFFFFFFFu, lm0, 2));
        lm1 = fmaxf(lm1, __shfl_xor_sync(0xFFFFFFFFu, lm1, 1));
        lm1 = fmaxf(lm1, __shfl_xor_sync(0xFFFFFFFFu, lm1, 2));

        const float mn0 = fmaxf(m0, lm0), mn1 = fmaxf(m1, lm1);
        const float corr0 = __expf(m0 - mn0), corr1 = __expf(m1 - mn1);
        m0 = mn0; m1 = mn1;

        // ---- exp, row sums, stage P (tf32) ----
        float ls0 = 0.f, ls1 = 0.f;
        #pragma unroll
        for (int nt = 0; nt < 8; nt++) {
            float p0 = __expf(s[nt][0] - mn0);
            float p1 = __expf(s[nt][1] - mn0);
            float p2 = __expf(s[nt][2] - mn1);
            float p3 = __expf(s[nt][3] - mn1);
            ls0 += p0 + p1; ls1 += p2 + p3;
            float2 vlo, vhi;
            vlo.x = __uint_as_float(f2tf32(p0));
            vlo.y = __uint_as_float(f2tf32(p1));
            vhi.x = __uint_as_float(f2tf32(p2));
            vhi.y = __uint_as_float(f2tf32(p3));
            *(float2*)&Pw[grp * PPITCH + nt * 8 + 2 * qid] = vlo;
            *(float2*)&Pw[(grp + 8) * PPITCH + nt * 8 + 2 * qid] = vhi;
        }
        ls0 += __shfl_xor_sync(0xFFFFFFFFu, ls0, 1);
        ls0 += __shfl_xor_sync(0xFFFFFFFFu, ls0, 2);
        ls1 += __shfl_xor_sync(0xFFFFFFFFu, ls1, 1);
        ls1 += __shfl_xor_sync(0xFFFFFFFFu, ls1, 2);
        l0 = l0 * corr0 + ls0;
        l1 = l1 * corr1 + ls1;

        #pragma unroll
        for (int nt = 0; nt < 8; nt++) {
            o[nt][0] *= corr0; o[nt][1] *= corr0;
            o[nt][2] *= corr1; o[nt][3] *= corr1;
        }

        __syncwarp();

        // ---- O += P @ V ----
        #pragma unroll
        for (int ks = 0; ks < 8; ks++) {
            const int k = ks * 8;
            uint32_t a0 = __float_as_uint(Pw[grp * PPITCH + k + qid]);
            uint32_t a1 = __float_as_uint(Pw[(grp + 8) * PPITCH + k + qid]);
            uint32_t a2 = __float_as_uint(Pw[grp * PPITCH + k + qid + 4]);
            uint32_t a3 = __float_as_uint(Pw[(grp + 8) * PPITCH + k + qid + 4]);
            #pragma unroll
            for (int nt = 0; nt < 8; nt++) {
                const int cb = nt * 8 + grp;
                uint32_t b0 = __float_as_uint(Vs[(k + qid) * VPITCH + cb]);
                uint32_t b1 = __float_as_uint(Vs[(k + qid + 4) * VPITCH + cb]);
                mma_tf32(o[nt], a0, a1, a2, a3, b0, b1);
            }
        }
        __syncthreads();   // stage p free for reuse; P strip reads done
    }

    // ---- epilogue: normalize, tf32-round (for O-proj), scatter ----
    const int b = bh >> 4, h = bh & (NH - 1);
    const float inv0 = 1.f / l0, inv1 = 1.f / l1;
    const int s_lo = q0 + wid * 16 + grp;
    const int s_hi = s_lo + 8;
    #pragma unroll
    for (int nt = 0; nt < 8; nt++) {
        const int col = h * HD + nt * 8 + 2 * qid;
        float2 vlo, vhi;
        vlo.x = __uint_as_float(f2tf32(o[nt][0] * inv0));
        vlo.y = __uint_as_float(f2tf32(o[nt][1] * inv0));
        vhi.x = __uint_as_float(f2tf32(o[nt][2] * inv1));
        vhi.y = __uint_as_float(f2tf32(o[nt][3] * inv1));
        *(float2*)&g_ao[((size_t)(b * SEQ + s_lo)) * DM + col] = vlo;
        *(float2*)&g_ao[((size_t)(b * SEQ + s_hi)) * DM + col] = vhi;
    }
}

// ---------------------------------------------------------------------------
extern "C" void kernel_launch(void* const* d_in, const int* in_sizes, int n_in,
                              void* d_out, int out_size)
{
    const float* x  = (const float*)d_in[0];
    const float* Wq = (const float*)d_in[1];
    const float* bq = (const float*)d_in[2];
    const float* Wk = (const float*)d_in[3];
    const float* bk = (const float*)d_in[4];
    const float* Wv = (const float*)d_in[5];
    const float* bv = (const float*)d_in[6];
    const float* Wo = (const float*)d_in[7];
    const float* bo = (const float*)d_in[8];

    cudaFuncSetAttribute(gemm_mma<0>,
                         cudaFuncAttributeMaxDynamicSharedMemorySize, GEMM_SMEM_BYTES);
    cudaFuncSetAttribute(gemm_mma<3>,
                         cudaFuncAttributeMaxDynamicSharedMemorySize, GEMM_SMEM_BYTES);
    cudaFuncSetAttribute(attn_mma,
                         cudaFuncAttributeMaxDynamicSharedMemorySize, ATTN_SMEM_BYTES);

    prep_kernel<<<(NX4 + 4 * NW4) / 256, 256>>>(x, Wq, Wk, Wv, Wo);

    gemm_mma<0><<<dim3(DM / 128, MTOT / 128, 3), 256, GEMM_SMEM_BYTES>>>(
        bq, bk, bv, nullptr);

    attn_mma<<<dim3(SEQ / 64, BATCH * NH), 128, ATTN_SMEM_BYTES>>>();

    gemm_mma<3><<<dim3(DM / 128, MTOT / 128, 1), 256, GEMM_SMEM_BYTES>>>(
        bo, nullptr, nullptr, (float*)d_out);
}

// round 11
// speedup vs baseline: 5.6784x; 1.6081x over previous
#include <cuda_runtime.h>
#include <cuda_fp16.h>
#include <cstdint>

#define DM    1024
#define NH    16
#define HD    64
#define BATCH 2
#define SEQ   2048
#define MTOT  (BATCH*SEQ)   // 4096

// Scratch (allocation-free rule: __device__ globals)
__device__ __half g_qh [(long long)BATCH*NH*SEQ*HD];  // [b,h,s,hd]
__device__ __half g_kh [(long long)BATCH*NH*SEQ*HD];  // [b,h,s,hd]
__device__ __half g_vt [(long long)BATCH*NH*HD*SEQ];  // [b,h,hd,s]  (transposed!)
__device__ __half g_aoh[(long long)MTOT*DM];          // [b*s, d]
__device__ __half g_xh [(long long)MTOT*DM];          // x as fp16
__device__ __half g_WhT[(long long)4*DM*DM];          // W^T: [w][n][k]

__device__ __forceinline__ uint32_t smem_u32(const void* p) {
    uint32_t a;
    asm("{ .reg .u64 t; cvta.to.shared.u64 t, %1; cvt.u32.u64 %0, t; }"
        : "=r"(a) : "l"(p));
    return a;
}

__device__ __forceinline__ void cp16(uint32_t dst, const void* src) {
    asm volatile("cp.async.cg.shared.global [%0], [%1], 16;"
                 :: "r"(dst), "l"(src) : "memory");
}
#define CP_COMMIT() asm volatile("cp.async.commit_group;" ::: "memory")
#define CP_WAIT(n)  asm volatile("cp.async.wait_group %0;" :: "n"(n) : "memory")

__device__ __forceinline__ void mma_f16(float c[4], uint32_t a0, uint32_t a1,
                                        uint32_t a2, uint32_t a3,
                                        uint32_t b0, uint32_t b1) {
    asm volatile(
        "mma.sync.aligned.m16n8k16.row.col.f32.f16.f16.f32 "
        "{%0,%1,%2,%3}, {%4,%5,%6,%7}, {%8,%9}, {%0,%1,%2,%3};"
        : "+f"(c[0]), "+f"(c[1]), "+f"(c[2]), "+f"(c[3])
        : "r"(a0), "r"(a1), "r"(a2), "r"(a3), "r"(b0), "r"(b1));
}

// ===========================================================================
// Prep 1: x -> fp16.   Prep 2: W -> fp16 transposed [n][k].
// ===========================================================================
__global__ void __launch_bounds__(256)
prep_x(const float* __restrict__ x)
{
    const int i = blockIdx.x * blockDim.x + threadIdx.x;   // 1M threads, 4 floats each
    float4 v = ((const float4*)x)[i];
    ((__half2*)g_xh)[i * 2 + 0] = __floats2half2_rn(v.x, v.y);
    ((__half2*)g_xh)[i * 2 + 1] = __floats2half2_rn(v.z, v.w);
}

__global__ void __launch_bounds__(256)
prep_wt(const float* __restrict__ wq, const float* __restrict__ wk,
        const float* __restrict__ wv, const float* __restrict__ wo)
{
    __shared__ float s[32][33];
    const int w = blockIdx.z;
    const float* W = (w == 0) ? wq : (w == 1) ? wk : (w == 2) ? wv : wo;
    const int n0 = blockIdx.x * 32, k0 = blockIdx.y * 32;
    const int tx = threadIdx.x & 31, ty = threadIdx.x >> 5;   // 32 x 8
    #pragma unroll
    for (int r = 0; r < 4; r++)
        s[ty + r * 8][tx] = W[(size_t)(k0 + ty + r * 8) * DM + n0 + tx];
    __syncthreads();
    #pragma unroll
    for (int r = 0; r < 4; r++)
        g_WhT[(size_t)w * DM * DM + (size_t)(n0 + ty + r * 8) * DM + k0 + tx] =
            __float2half_rn(s[tx][ty + r * 8]);
}

// ===========================================================================
// FP16 mma.sync GEMM, 3-stage cp.async pipeline, one barrier per K-iter.
// C[M,N] = A[M,1024] @ W[1024,N] + bias.  128x128 tile, 8 warps, 64x32/warp.
// K-iter 32 (2 x m16n8k16).  A [m][k] k-contig halves; W as Wt [n][k] k-contig.
// MODE 0: A=g_xh, out z=0/1 -> g_qh/g_kh [b,h,s,hd]; z=2 -> g_vt [b,h,hd,s]
// MODE 3: A=g_aoh, out=d_out (fp32, linear)
// ===========================================================================
#define APITCH 56                    // halves; 112 B row (16-mult, conflict-free)
#define ATILEH (128*APITCH)          // 7168 halves
#define BUFH   (2*ATILEH)            // A + Wt per stage = 14336 halves
#define NSTAGE 3
#define GEMM_SMEM_BYTES (NSTAGE*BUFH*2)   // 86016
#define NKT (DM/32)

template<int MODE>
__global__ void __launch_bounds__(256, 2)
gemm_mma(const float* __restrict__ b0,
         const float* __restrict__ b1,
         const float* __restrict__ b2,
         float* __restrict__ Cout)
{
    extern __shared__ __half smh[];
    const uint32_t sb = smem_u32(smh);

    const int t   = threadIdx.x;
    const int wid = t >> 5, lane = t & 31;
    const int grp = lane >> 2, qid = lane & 3;
    const int wr  = wid & 1, wc = wid >> 1;
    const int bn  = blockIdx.x * 128, bm = blockIdx.y * 128;
    const int z   = (MODE == 3) ? 3 : blockIdx.z;

    const __half* Ap = (MODE == 3) ? g_aoh : g_xh;
    const __half* Wt = g_WhT + (size_t)z * DM * DM;
    const float* bias = (MODE == 3) ? b0 : (z == 0) ? b0 : (z == 1) ? b1 : b2;

    float c[4][4][4];
    #pragma unroll
    for (int mt = 0; mt < 4; mt++)
        #pragma unroll
        for (int nt = 0; nt < 4; nt++)
            #pragma unroll
            for (int i = 0; i < 4; i++) c[mt][nt][i] = 0.f;

    auto loadA = [&](int p, int kt) {
        #pragma unroll
        for (int i = 0; i < 2; i++) {
            int idx = t + 256 * i;
            int row = idx >> 2, c4 = idx & 3;            // 128 rows x 4 16B-chunks
            cp16(sb + (uint32_t)(p * BUFH + row * APITCH + c4 * 8) * 2,
                 &Ap[(size_t)(bm + row) * DM + kt * 32 + c4 * 8]);
        }
    };
    auto loadW = [&](int p, int kt) {
        #pragma unroll
        for (int i = 0; i < 2; i++) {
            int idx = t + 256 * i;
            int row = idx >> 2, c4 = idx & 3;            // 128 n-rows x 4 chunks
            cp16(sb + (uint32_t)(p * BUFH + ATILEH + row * APITCH + c4 * 8) * 2,
                 &Wt[(size_t)(bn + row) * DM + kt * 32 + c4 * 8]);
        }
    };

    loadA(0, 0); loadW(0, 0); CP_COMMIT();
    loadA(1, 1); loadW(1, 1); CP_COMMIT();

    int cs = 0, ls = 2;
    for (int kt = 0; kt < NKT; kt++) {
        if (kt + 1 < NKT) { CP_WAIT(1); } else { CP_WAIT(0); }
        __syncthreads();

        if (kt + 2 < NKT) {
            loadA(ls, kt + 2); loadW(ls, kt + 2); CP_COMMIT();
            ls = (ls + 1 == NSTAGE) ? 0 : ls + 1;
        }

        const __half* As = smh + cs * BUFH;
        const __half* Ws = smh + cs * BUFH + ATILEH;
        #pragma unroll
        for (int ks = 0; ks < 2; ks++) {
            const int kh = ks * 16;
            uint32_t af[4][4];
            #pragma unroll
            for (int mt = 0; mt < 4; mt++) {
                const __half* ab = As + (wr * 64 + mt * 16 + grp) * APITCH + kh + 2 * qid;
                af[mt][0] = *(const uint32_t*)(ab);
                af[mt][1] = *(const uint32_t*)(ab + 8 * APITCH);
                af[mt][2] = *(const uint32_t*)(ab + 8);
                af[mt][3] = *(const uint32_t*)(ab + 8 * APITCH + 8);
            }
            uint32_t bf[4][2];
            #pragma unroll
            for (int nt = 0; nt < 4; nt++) {
                const __half* bb = Ws + (wc * 32 + nt * 8 + grp) * APITCH + kh + 2 * qid;
                bf[nt][0] = *(const uint32_t*)(bb);
                bf[nt][1] = *(const uint32_t*)(bb + 8);
            }
            #pragma unroll
            for (int mt = 0; mt < 4; mt++)
                #pragma unroll
                for (int nt = 0; nt < 4; nt++)
                    mma_f16(c[mt][nt], af[mt][0], af[mt][1], af[mt][2], af[mt][3],
                            bf[nt][0], bf[nt][1]);
        }
        cs = (cs + 1 == NSTAGE) ? 0 : cs + 1;
    }

    #pragma unroll
    for (int mt = 0; mt < 4; mt++) {
        #pragma unroll
        for (int nt = 0; nt < 4; nt++) {
            const int gc = bn + wc * 32 + nt * 8 + 2 * qid;
            const float bx = bias[gc], by = bias[gc + 1];
            #pragma unroll
            for (int half = 0; half < 2; half++) {
                const int gr = bm + wr * 64 + mt * 16 + grp + half * 8;
                const float vx = c[mt][nt][half * 2 + 0] + bx;
                const float vy = c[mt][nt][half * 2 + 1] + by;
                if (MODE == 3) {
                    float2 v; v.x = vx; v.y = vy;
                    *(float2*)&Cout[(size_t)gr * DM + gc] = v;
                } else {
                    const int b = gr >> 11, s = gr & (SEQ - 1);
                    const int h = gc >> 6,  hd = gc & (HD - 1);
                    if (z == 0) {
                        *(__half2*)&g_qh[((size_t)((b * NH + h) * SEQ + s)) * HD + hd] =
                            __floats2half2_rn(vx, vy);
                    } else if (z == 1) {
                        *(__half2*)&g_kh[((size_t)((b * NH + h) * SEQ + s)) * HD + hd] =
                            __floats2half2_rn(vx, vy);
                    } else {
                        // V transposed: [b,h,hd,s]
                        __half* vtp = g_vt + ((size_t)(b * NH + h) * HD) * SEQ;
                        vtp[(size_t)(hd + 0) * SEQ + s] = __float2half_rn(vx);
                        vtp[(size_t)(hd + 1) * SEQ + s] = __float2half_rn(vy);
                    }
                }
            }
        }
    }
}

// ===========================================================================
// FP16 mma.sync flash attention, cp.async double-buffered K/V(transposed).
// BQ=BK=64, 128 threads = 4 warps.  grid: (SEQ/64, BATCH*NH), reversed qt.
// ===========================================================================
#define QP 72                         // half pitch: 144 B (16-mult, conflict-free)
#define SMQ   0
#define SMKV  (64*QP)                 // 4608 halves
#define KVH   (2*64*QP)               // 9216 halves per stage (K + Vt)
#define SMP   (SMKV + 2*KVH)          // 23040
#define ATTN_H (SMP + 4*16*QP)        // 27648 halves
#define ATTN_SMEM_BYTES (ATTN_H*2)    // 55296

__global__ void __launch_bounds__(128)
attn_mma()
{
    extern __shared__ __half smh[];
    const uint32_t sb = smem_u32(smh);

    const int t    = threadIdx.x;
    const int wid  = t >> 5, lane = t & 31;
    const int grp  = lane >> 2, qid = lane & 3;
    const int qt   = gridDim.x - 1 - blockIdx.x;
    const int bh   = blockIdx.y;
    const int q0   = qt * 64;

    const __half* Qg  = g_qh + ((size_t)bh * SEQ + q0) * HD;
    const __half* Kg  = g_kh + (size_t)bh * SEQ * HD;
    const __half* Vtg = g_vt + (size_t)bh * HD * SEQ;

    auto loadKV = [&](int p, int kt) {
        const int k0 = kt * 64;
        const uint32_t kb = sb + (uint32_t)(SMKV + p * KVH) * 2;
        #pragma unroll
        for (int i = 0; i < 4; i++) {
            int idx = t + 128 * i;
            int row = idx >> 3, c8 = idx & 7;       // 64 rows x 8 chunks (16B)
            cp16(kb + (uint32_t)(row * QP + c8 * 8) * 2,
                 &Kg[(size_t)(k0 + row) * HD + c8 * 8]);
        }
        #pragma unroll
        for (int i = 0; i < 4; i++) {
            int idx = t + 128 * i;
            int d = idx >> 3, c8 = idx & 7;         // Vt: 64 d-rows x 8 s-chunks
            cp16(kb + (uint32_t)(64 * QP + d * QP + c8 * 8) * 2,
                 &Vtg[(size_t)d * SEQ + k0 + c8 * 8]);
        }
    };

    #pragma unroll
    for (int i = 0; i < 4; i++) {
        int idx = t + 128 * i;
        int row = idx >> 3, c8 = idx & 7;
        cp16(sb + (uint32_t)(SMQ + row * QP + c8 * 8) * 2,
             &Qg[(size_t)row * HD + c8 * 8]);
    }
    loadKV(0, 0);
    CP_COMMIT();

    float o[8][4];
    #pragma unroll
    for (int nt = 0; nt < 8; nt++)
        #pragma unroll
        for (int i = 0; i < 4; i++) o[nt][i] = 0.f;
    float m0 = -1e30f, m1 = -1e30f, l0 = 0.f, l1 = 0.f;

    __half* Pw = smh + SMP + wid * 16 * QP;

    const int ntiles = qt + 1;
    for (int kt = 0; kt < ntiles; kt++) {
        const int p = kt & 1;
        if (kt + 1 < ntiles) {
            loadKV(p ^ 1, kt + 1); CP_COMMIT();
            CP_WAIT(1);
        } else {
            CP_WAIT(0);
        }
        __syncthreads();

        const int k0 = kt * 64;
        const __half* Ks = smh + SMKV + p * KVH;
        const __half* Vs = Ks + 64 * QP;

        // ---- S = Q @ K^T : 4 x m16n8k16 k-steps, 8 n-tiles ----
        float s[8][4];
        #pragma unroll
        for (int nt = 0; nt < 8; nt++)
            #pragma unroll
            for (int i = 0; i < 4; i++) s[nt][i] = 0.f;

        const __half* Qs = smh + SMQ + (wid * 16) * QP;
        #pragma unroll
        for (int ks = 0; ks < 4; ks++) {
            const int kh = ks * 16;
            const __half* ab = Qs + grp * QP + kh + 2 * qid;
            uint32_t a0 = *(const uint32_t*)(ab);
            uint32_t a1 = *(const uint32_t*)(ab + 8 * QP);
            uint32_t a2 = *(const uint32_t*)(ab + 8);
            uint32_t a3 = *(const uint32_t*)(ab + 8 * QP + 8);
            #pragma unroll
            for (int nt = 0; nt < 8; nt++) {
                const __half* bb = Ks + (nt * 8 + grp) * QP + kh + 2 * qid;
                mma_f16(s[nt], a0, a1, a2, a3,
                        *(const uint32_t*)(bb), *(const uint32_t*)(bb + 8));
            }
        }

        // ---- scale + causal mask (diagonal tile only) + row max ----
        const int r_lo = q0 + wid * 16 + grp;
        const int r_hi = r_lo + 8;
        float lm0 = -1e30f, lm1 = -1e30f;
        #pragma unroll
        for (int nt = 0; nt < 8; nt++) {
            const int cg = k0 + nt * 8 + 2 * qid;
            #pragma unroll
            for (int i = 0; i < 4; i++) s[nt][i] *= 0.125f;
            if (kt == ntiles - 1) {
                if (cg     > r_lo) s[nt][0] = -1e30f;
                if (cg + 1 > r_lo) s[nt][1] = -1e30f;
                if (cg     > r_hi) s[nt][2] = -1e30f;
                if (cg + 1 > r_hi) s[nt][3] = -1e30f;
            }
            lm0 = fmaxf(lm0, fmaxf(s[nt][0], s[nt][1]));
            lm1 = fmaxf(lm1, fmaxf(s[nt][2], s[nt][3]));
        }
        lm0 = fmaxf(lm0, __shfl_xor_sync(0xFFFFFFFFu, lm0, 1));
        lm0 = fmaxf(lm0, __shfl_xor_sync(0xFFFFFFFFu, lm0, 2));
        lm1 = fmaxf(lm1, __shfl_xor_sync(0xFFFFFFFFu, lm1, 1));
        lm1 = fmaxf(lm1, __shfl_xor_sync(0xFFFFFFFFu, lm1, 2));

        const float mn0 = fmaxf(m0, lm0), mn1 = fmaxf(m1, lm1);
        const float corr0 = __expf(m0 - mn0), corr1 = __expf(m1 - mn1);
        m0 = mn0; m1 = mn1;

        // ---- exp, row sums, stage P (fp16) ----
        float ls0 = 0.f, ls1 = 0.f;
        #pragma unroll
        for (int nt = 0; nt < 8; nt++) {
            float p0 = __expf(s[nt][0] - mn0);
            float p1 = __expf(s[nt][1] - mn0);
            float p2 = __expf(s[nt][2] - mn1);
            float p3 = __expf(s[nt][3] - mn1);
            ls0 += p0 + p1; ls1 += p2 + p3;
            *(__half2*)&Pw[grp * QP + nt * 8 + 2 * qid]       = __floats2half2_rn(p0, p1);
            *(__half2*)&Pw[(grp + 8) * QP + nt * 8 + 2 * qid] = __floats2half2_rn(p2, p3);
        }
        ls0 += __shfl_xor_sync(0xFFFFFFFFu, ls0, 1);
        ls0 += __shfl_xor_sync(0xFFFFFFFFu, ls0, 2);
        ls1 += __shfl_xor_sync(0xFFFFFFFFu, ls1, 1);
        ls1 += __shfl_xor_sync(0xFFFFFFFFu, ls1, 2);
        l0 = l0 * corr0 + ls0;
        l1 = l1 * corr1 + ls1;

        #pragma unroll
        for (int nt = 0; nt < 8; nt++) {
            o[nt][0] *= corr0; o[nt][1] *= corr0;
            o[nt][2] *= corr1; o[nt][3] *= corr1;
        }

        __syncwarp();

        // ---- O += P @ V : a from P strip, b from Vt (kk-contig) ----
        #pragma unroll
        for (int ks = 0; ks < 4; ks++) {
            const int kh = ks * 16;
            const __half* ab = Pw + grp * QP + kh + 2 * qid;
            uint32_t a0 = *(const uint32_t*)(ab);
            uint32_t a1 = *(const uint32_t*)(ab + 8 * QP);
            uint32_t a2 = *(const uint32_t*)(ab + 8);
            uint32_t a3 = *(const uint32_t*)(ab + 8 * QP + 8);
            #pragma unroll
            for (int nt = 0; nt < 8; nt++) {
                const __half* bb = Vs + (nt * 8 + grp) * QP + kh + 2 * qid;
                mma_f16(o[nt], a0, a1, a2, a3,
                        *(const uint32_t*)(bb), *(const uint32_t*)(bb + 8));
            }
        }
        __syncthreads();
    }

    // ---- epilogue: normalize, fp16-round, scatter to g_aoh [b*s, d] ----
    const int b = bh >> 4, h = bh & (NH - 1);
    const float inv0 = 1.f / l0, inv1 = 1.f / l1;
    const int s_lo = q0 + wid * 16 + grp;
    const int s_hi = s_lo + 8;
    #pragma unroll
    for (int nt = 0; nt < 8; nt++) {
        const int col = h * HD + nt * 8 + 2 * qid;
        *(__half2*)&g_aoh[((size_t)(b * SEQ + s_lo)) * DM + col] =
            __floats2half2_rn(o[nt][0] * inv0, o[nt][1] * inv0);
        *(__half2*)&g_aoh[((size_t)(b * SEQ + s_hi)) * DM + col] =
            __floats2half2_rn(o[nt][2] * inv1, o[nt][3] * inv1);
    }
}

// ---------------------------------------------------------------------------
extern "C" void kernel_launch(void* const* d_in, const int* in_sizes, int n_in,
                              void* d_out, int out_size)
{
    const float* x  = (const float*)d_in[0];
    const float* Wq = (const float*)d_in[1];
    const float* bq = (const float*)d_in[2];
    const float* Wk = (const float*)d_in[3];
    const float* bk = (const float*)d_in[4];
    const float* Wv = (const float*)d_in[5];
    const float* bv = (const float*)d_in[6];
    const float* Wo = (const float*)d_in[7];
    const float* bo = (const float*)d_in[8];

    cudaFuncSetAttribute(gemm_mma<0>,
                         cudaFuncAttributeMaxDynamicSharedMemorySize, GEMM_SMEM_BYTES);
    cudaFuncSetAttribute(gemm_mma<3>,
                         cudaFuncAttributeMaxDynamicSharedMemorySize, GEMM_SMEM_BYTES);
    cudaFuncSetAttribute(attn_mma,
                         cudaFuncAttributeMaxDynamicSharedMemorySize, ATTN_SMEM_BYTES);

    prep_x<<<MTOT * DM / 4 / 256, 256>>>(x);
    prep_wt<<<dim3(DM / 32, DM / 32, 4), 256>>>(Wq, Wk, Wv, Wo);

    gemm_mma<0><<<dim3(DM / 128, MTOT / 128, 3), 256, GEMM_SMEM_BYTES>>>(
        bq, bk, bv, nullptr);

    attn_mma<<<dim3(SEQ / 64, BATCH * NH), 128, ATTN_SMEM_BYTES>>>();

    gemm_mma<3><<<dim3(DM / 128, MTOT / 128, 1), 256, GEMM_SMEM_BYTES>>>(
        bo, nullptr, nullptr, (float*)d_out);
}